// round 14
// baseline (speedup 1.0000x reference)
#include <cuda_runtime.h>
#include <cstdint>

// Problem dims
#define TT    512
#define BB    32
#define DD    512
#define HH    512
#define FEAT  2048
#define G4H   2048   // 4*H

// Output layout (fp32, tuple order: out, h_n, c_n, x, lens_s)
#define OUT_OFF  0
#define HN_OFF   16777216
#define CN_OFF   (16777216 + 32768)
#define X_OFF    (16777216 + 65536)
#define LENS_OFF (X_OFF + 8388608)

#define GSZ       (512*32*2048)        // per-direction G size (floats)
#define WCHUNKS   524288               // frag chunks per weight matrix

// scan smem (dynamic): h_s[2][16*544], g_sm[2][16*36], part[8][576]
#define HS_SZ     (16 * 544)
#define GSM_SZ    (16 * 36)
#define H0_OFF    0
#define H1_OFF    HS_SZ
#define GS0_OFF   (2 * HS_SZ)
#define GS1_OFF   (2 * HS_SZ + GSM_SZ)
#define PART_OFF  (2 * HS_SZ + 2 * GSM_SZ)
#define SCAN_SMEM ((2 * HS_SZ + 2 * GSM_SZ + 8 * 576) * 4)

// ---------------- device scratch ---------------------------------------
__device__ float    g_G[2 * GSZ];          // input-gate preactivations (268MB)
__device__ float    g_hring[2][4][BB][HH]; // h ring buffer, depth 4
__device__ unsigned g_done[2][TT][4];      // per (dir, step, pair) counters
__device__ int      g_order[BB];
__device__ int      g_lens[BB];
__device__ uint4    g_wfc[WCHUNKS];        // fc_w   frag-layout (hi/lo tf32)
__device__ uint4    g_wih[2][WCHUNKS];     // w_ih_f / w_ih_b frag-layout

// ---------------- helpers ----------------------------------------------
__device__ __forceinline__ uint32_t f2tf32(float v) {
    uint32_t r;
    asm("cvt.rna.tf32.f32 %0, %1;" : "=r"(r) : "f"(v));
    return r;
}

__device__ __forceinline__ void mma_tf32(float4& c, const uint4& a,
                                         uint32_t b0, uint32_t b1) {
    asm volatile(
        "mma.sync.aligned.m16n8k8.row.col.f32.tf32.tf32.f32 "
        "{%0,%1,%2,%3}, {%4,%5,%6,%7}, {%8,%9}, {%0,%1,%2,%3};"
        : "+f"(c.x), "+f"(c.y), "+f"(c.z), "+f"(c.w)
        : "r"(a.x), "r"(a.y), "r"(a.z), "r"(a.w), "r"(b0), "r"(b1));
}

#define FMA2(acc, a, b) \
    asm("fma.rn.f32x2 %0, %1, %2, %0;" : "+l"(acc) : "l"(a), "l"(b))

__device__ __forceinline__ float sum2(unsigned long long v) {
    float lo, hi;
    asm("mov.b64 {%0,%1}, %2;" : "=f"(lo), "=f"(hi) : "l"(v));
    return lo + hi;
}

__device__ __forceinline__ unsigned long long packf2(float a, float b) {
    unsigned long long u;
    asm("mov.b64 %0, {%1,%2};" : "=l"(u) : "f"(a), "f"(b));
    return u;
}

// ---------------- reset / sort kernel ----------------------------------
__global__ void k_reset(const int* __restrict__ seq_lens,
                        const float* __restrict__ h0,
                        float* __restrict__ out) {
    int tid = threadIdx.x;
    if (tid == 0) {
        unsigned used = 0u;
        for (int pos = 0; pos < BB; pos++) {
            int best = -1, bl = -1;
            for (int i = 0; i < BB; i++) {
                if (used & (1u << i)) continue;
                int L = seq_lens[i];
                if (L > bl) { bl = L; best = i; }
            }
            used |= 1u << best;
            g_order[pos] = best;
            g_lens[pos]  = bl;
            out[LENS_OFF + pos] = (float)bl;
        }
    }
    for (int i = tid; i < 2 * TT * 4; i += blockDim.x)
        ((unsigned*)g_done)[i] = 0u;
    for (int i = tid; i < 2 * 16384; i += blockDim.x) {
        int dir = i >> 14;
        int r   = i & 16383;
        g_hring[dir][0][r >> 9][r & 511] = h0[i];
    }
}

// ---------------- bulk zero of the `out` region -------------------------
__global__ void __launch_bounds__(256) k_zero(float* __restrict__ out) {
    size_t i = ((size_t)blockIdx.x * 256 + threadIdx.x) * 4;
    *(float4*)&out[OUT_OFF + i] = make_float4(0.f, 0.f, 0.f, 0.f);
}

// ---------------- weight pre-conversion to frag layout ------------------
__global__ void __launch_bounds__(256) k_prep(
    const float* __restrict__ fcw, const float* __restrict__ wihf,
    const float* __restrict__ wihb) {
    int z = blockIdx.y;
    const float* src = (z == 0) ? fcw : ((z == 1) ? wihf : wihb);
    uint4* dst = (z == 0) ? g_wfc : g_wih[z - 1];
    int K     = (z == 0) ? FEAT : DD;
    int nKtm1 = (z == 0) ? 63 : 15;
    int nKtsh = (z == 0) ? 6 : 4;

    int c    = blockIdx.x * 256 + threadIdx.x;
    int lane = c & 31;
    int hl   = (c >> 5) & 1;
    int s    = (c >> 6) & 3;
    int q    = (c >> 8) & 3;
    int tile = c >> 10;
    int qt   = tile & nKtm1;
    int r64  = tile >> nKtsh;
    int g    = lane >> 2, tg = lane & 3;
    int m0   = r64 * 64 + s * 16;
    int kk   = qt * 32 + q * 8 + tg;

    float v0 = src[(size_t)(m0 + g)     * K + kk];
    float v1 = src[(size_t)(m0 + g + 8) * K + kk];
    float v2 = src[(size_t)(m0 + g)     * K + kk + 4];
    float v3 = src[(size_t)(m0 + g + 8) * K + kk + 4];
    uint4 o;
    if (hl == 0) {
        o.x = f2tf32(v0); o.y = f2tf32(v1); o.z = f2tf32(v2); o.w = f2tf32(v3);
    } else {
        o.x = f2tf32(v0 - __uint_as_float(f2tf32(v0)));
        o.y = f2tf32(v1 - __uint_as_float(f2tf32(v1)));
        o.z = f2tf32(v2 - __uint_as_float(f2tf32(v2)));
        o.w = f2tf32(v3 - __uint_as_float(f2tf32(v3)));
    }
    dst[c] = o;
}

// ================= MMA GEMMs (A = weights frag-global, B = data rows) ==
__device__ __forceinline__ void sts_b_convert(uint4* Bsm, const float4* braw,
                                              int r, int qp) {
    int xr = (r & 3) ^ ((r >> 2) & 3);
#pragma unroll
    for (int oo = 0; oo < 2; oo++) {
        float f[8];
        f[0] = braw[oo*2].x;   f[1] = braw[oo*2].y;
        f[2] = braw[oo*2].z;   f[3] = braw[oo*2].w;
        f[4] = braw[oo*2+1].x; f[5] = braw[oo*2+1].y;
        f[6] = braw[oo*2+1].z; f[7] = braw[oo*2+1].w;
        uint32_t hi[8], lo[8];
#pragma unroll
        for (int p = 0; p < 8; p++) {
            hi[p] = f2tf32(f[p]);
            lo[p] = f2tf32(f[p] - __uint_as_float(hi[p]));
        }
        int q = qp * 2 + oo;
        int sbase = q * 256 + r * 4;
#pragma unroll
        for (int t2 = 0; t2 < 4; t2++) {
            uint4 ch;
            ch.x = hi[t2]; ch.y = hi[t2 + 4];
            ch.z = lo[t2]; ch.w = lo[t2 + 4];
            Bsm[sbase + (t2 ^ xr)] = ch;
        }
    }
}

__device__ __forceinline__ void mma_ktile(const uint4* As, const uint4* Bsm,
                                          float4 c[2][4], int wm, int wn,
                                          int lane, int g, int tg) {
#pragma unroll
    for (int q = 0; q < 4; q++) {
        uint4 ah[2], al[2], bq[4];
#pragma unroll
        for (int mi = 0; mi < 2; mi++) {
            int s = wm * 2 + mi;
            ah[mi] = As[((q * 4 + s) * 2 + 0) * 32 + lane];
            al[mi] = As[((q * 4 + s) * 2 + 1) * 32 + lane];
        }
#pragma unroll
        for (int ni = 0; ni < 4; ni++) {
            int rr = wn * 32 + ni * 8 + g;
            int sw = tg ^ (rr & 3) ^ ((rr >> 2) & 3);
            bq[ni] = Bsm[q * 256 + rr * 4 + sw];
        }
#pragma unroll
        for (int mi = 0; mi < 2; mi++)
#pragma unroll
            for (int ni = 0; ni < 4; ni++) {
                mma_tf32(c[mi][ni], ah[mi], bq[ni].x, bq[ni].y);
                mma_tf32(c[mi][ni], ah[mi], bq[ni].z, bq[ni].w);
                mma_tf32(c[mi][ni], al[mi], bq[ni].x, bq[ni].y);
            }
    }
}

// GEMM1: x[t,j,ch] = mask * (cnn[lookup[order[j],t]] @ fc_w^T + fc_b)[ch]
__global__ void __launch_bounds__(128) k_gemm1(
    const float* __restrict__ cnn, const float* __restrict__ fcb,
    const int* __restrict__ lookup, float* __restrict__ xout) {
    __shared__ uint4 As[1024];
    __shared__ uint4 Bsm[1024];
    __shared__ int   simg[64];

    int j   = blockIdx.z;
    int t0  = blockIdx.y * 64;
    int m0  = blockIdx.x * 64;
    int tid = threadIdx.x;
    int len = g_lens[j];

    if (t0 >= len) {
        for (int i = tid; i < 1024; i += 128) {
            int r  = i >> 4;
            int cc = (i & 15) * 4;
            int t  = t0 + r;
            *(float4*)&xout[((size_t)t * BB + j) * DD + m0 + cc] =
                make_float4(0.f, 0.f, 0.f, 0.f);
        }
        return;
    }
    if (tid < 64) simg[tid] = lookup[g_order[j] * TT + t0 + tid];
    __syncthreads();

    int lane = tid & 31;
    int w    = tid >> 5;
    int wm   = w >> 1, wn = w & 1;
    int g    = lane >> 2, tg = lane & 3;
    int r    = tid >> 1, qp = tid & 1;
    size_t brow = (size_t)simg[r] * FEAT;

    float4 c[2][4];
#pragma unroll
    for (int mi = 0; mi < 2; mi++)
#pragma unroll
        for (int ni = 0; ni < 4; ni++) c[mi][ni] = make_float4(0.f,0.f,0.f,0.f);

    uint4  areg[8];
    float4 braw[4];
    {
        const uint4* at = g_wfc + ((size_t)blockIdx.x * 64 + 0) * 1024;
#pragma unroll
        for (int u = 0; u < 8; u++) areg[u] = at[tid + 128 * u];
        int kb = qp * 16;
#pragma unroll
        for (int u = 0; u < 4; u++)
            braw[u] = *(const float4*)&cnn[brow + kb + u * 4];
    }

    for (int kt = 0; kt < 64; kt++) {
        __syncthreads();
#pragma unroll
        for (int u = 0; u < 8; u++) As[tid + 128 * u] = areg[u];
        sts_b_convert(Bsm, braw, r, qp);
        __syncthreads();
        if (kt + 1 < 64) {
            const uint4* at = g_wfc + ((size_t)blockIdx.x * 64 + kt + 1) * 1024;
#pragma unroll
            for (int u = 0; u < 8; u++) areg[u] = at[tid + 128 * u];
            int kb = (kt + 1) * 32 + qp * 16;
#pragma unroll
            for (int u = 0; u < 4; u++)
                braw[u] = *(const float4*)&cnn[brow + kb + u * 4];
        }
        mma_ktile(As, Bsm, c, wm, wn, lane, g, tg);
    }

#pragma unroll
    for (int mi = 0; mi < 2; mi++) {
        int ch  = m0 + wm * 32 + mi * 16 + g;
        float b0 = fcb[ch], b8 = fcb[ch + 8];
#pragma unroll
        for (int ni = 0; ni < 4; ni++) {
            int tA = t0 + wn * 32 + ni * 8 + 2 * tg;
            bool v0 = (tA < len), v1 = (tA + 1 < len);
            size_t r0o = ((size_t)tA * BB + j) * DD;
            size_t r1o = ((size_t)(tA + 1) * BB + j) * DD;
            xout[r0o + ch]     = v0 ? c[mi][ni].x + b0 : 0.f;
            xout[r1o + ch]     = v1 ? c[mi][ni].y + b0 : 0.f;
            xout[r0o + ch + 8] = v0 ? c[mi][ni].z + b8 : 0.f;
            xout[r1o + ch + 8] = v1 ? c[mi][ni].w + b8 : 0.f;
        }
    }
}

// GEMM2: G[dir][j,t,ch] = x[t,j,:] @ w_ih[dir]^T
__global__ void __launch_bounds__(128) k_gemm2(const float* __restrict__ x) {
    __shared__ uint4 As[1024];
    __shared__ uint4 Bsm[1024];

    int dir = blockIdx.z;
    int j   = blockIdx.y >> 3;
    int t0  = (blockIdx.y & 7) * 64;
    int m0  = blockIdx.x * 64;
    int tid = threadIdx.x;
    int len = g_lens[j];
    if (t0 >= len) return;

    int lane = tid & 31;
    int w    = tid >> 5;
    int wm   = w >> 1, wn = w & 1;
    int g    = lane >> 2, tg = lane & 3;
    int r    = tid >> 1, qp = tid & 1;
    size_t brow = ((size_t)(t0 + r) * BB + j) * DD;

    float4 c[2][4];
#pragma unroll
    for (int mi = 0; mi < 2; mi++)
#pragma unroll
        for (int ni = 0; ni < 4; ni++) c[mi][ni] = make_float4(0.f,0.f,0.f,0.f);

    const uint4* wbase = g_wih[dir];
    uint4  areg[8];
    float4 braw[4];
    {
        const uint4* at = wbase + ((size_t)blockIdx.x * 16 + 0) * 1024;
#pragma unroll
        for (int u = 0; u < 8; u++) areg[u] = at[tid + 128 * u];
        int kb = qp * 16;
#pragma unroll
        for (int u = 0; u < 4; u++)
            braw[u] = *(const float4*)&x[brow + kb + u * 4];
    }

    for (int kt = 0; kt < 16; kt++) {
        __syncthreads();
#pragma unroll
        for (int u = 0; u < 8; u++) As[tid + 128 * u] = areg[u];
        sts_b_convert(Bsm, braw, r, qp);
        __syncthreads();
        if (kt + 1 < 16) {
            const uint4* at = wbase + ((size_t)blockIdx.x * 16 + kt + 1) * 1024;
#pragma unroll
            for (int u = 0; u < 8; u++) areg[u] = at[tid + 128 * u];
            int kb = (kt + 1) * 32 + qp * 16;
#pragma unroll
            for (int u = 0; u < 4; u++)
                braw[u] = *(const float4*)&x[brow + kb + u * 4];
        }
        mma_ktile(As, Bsm, c, wm, wn, lane, g, tg);
    }

    float* Gd = g_G + (size_t)dir * GSZ;
#pragma unroll
    for (int mi = 0; mi < 2; mi++) {
        int ch = m0 + wm * 32 + mi * 16 + g;
#pragma unroll
        for (int ni = 0; ni < 4; ni++) {
            int tA = t0 + wn * 32 + ni * 8 + 2 * tg;
            size_t r0o = ((size_t)j * TT + tA) * G4H;
            size_t r1o = ((size_t)j * TT + tA + 1) * G4H;
            Gd[r0o + ch]     = c[mi][ni].x;
            Gd[r1o + ch]     = c[mi][ni].y;
            Gd[r0o + ch + 8] = c[mi][ni].z;
            Gd[r1o + ch + 8] = c[mi][ni].w;
        }
    }
}

// ---------------- persistent scan kernel (v8: 16-batch pair ticks) ------
// v7 protocol with pairs (16 batches) per tick: ~730 ticks instead of
// ~1225. Dep of (s+1,P) = (s,P), 2 ticks back -> prefetch slack 1 tick
// everywhere except the single-pair tail (fallback path, as v7).
__global__ void __launch_bounds__(256, 1) k_scan(
    const float* __restrict__ c0, const float* __restrict__ h0,
    const float* __restrict__ whhf, const float* __restrict__ whhb,
    const float* __restrict__ bihf, const float* __restrict__ bhhf,
    const float* __restrict__ bihb, const float* __restrict__ bhhb,
    float* __restrict__ out) {
    extern __shared__ float sm[];
    float* part = sm + PART_OFF;

    int bid  = blockIdx.x;
    int dir  = bid >> 6;
    int ctad = bid & 63;
    int hcb  = ctad * 8;
    int tid  = threadIdx.x;
    int w    = tid >> 5;
    int lane = tid & 31;
    int g4   = lane & 3;
    int ks   = lane >> 2;
    int hc   = hcb + w;

    const float* whh = dir ? whhb : whhf;
    ulonglong2 warr[16];
    {
        const float* wrow = whh + (size_t)(g4 * HH + hc) * HH + ks * 64;
#pragma unroll
        for (int i = 0; i < 16; i++) {
            float4 v = *(const float4*)(wrow + i * 4);
            warr[i].x = packf2(v.x, v.y);
            warr[i].y = packf2(v.z, v.w);
        }
    }
    float bias[4];
    {
        const float* bih = dir ? bihb : bihf;
        const float* bhh = dir ? bhhb : bhhf;
#pragma unroll
        for (int q = 0; q < 4; q++)
            bias[q] = bih[q * HH + hc] + bhh[q * HH + hc];
    }

    // pointwise state: thread (w, lane<16) owns batches {P*16+lane}
    float creg2[2], hreg2[2];
    int   lenb2[2];
    if (lane < 16) {
#pragma unroll
        for (int P = 0; P < 2; P++) {
            int b = P * 16 + lane;
            lenb2[P] = g_lens[b];
            creg2[P] = c0[dir * 16384 + b * HH + hc];
            hreg2[P] = h0[dir * 16384 + b * HH + hc];
        }
    }

    // G loader role: thread covers (lb, gate, ch) for b_local lb and lb+8
    int lb  = tid >> 5;
    int lg  = (tid & 31) >> 3;
    int lch = tid & 7;
    const float* Gd = g_G + (size_t)dir * GSZ;

    int plen[2];
    plen[0] = g_lens[0];
    plen[1] = g_lens[16];
    int maxlen = plen[0];

    // ---- prologue: stage tick (0, P=0) into buf 0 ----
    {
        const float* hin = &g_hring[dir][0][0][0];
#pragma unroll
        for (int i = 0; i < 8; i++) {
            int idx = tid + 256 * i;               // float4 idx, 2048 total
            float4 v = __ldcg((const float4*)&hin[idx * 4]);
            int b = idx >> 7;
            int k = (idx & 127) * 4;
            *(float4*)&sm[H0_OFF + b * 544 + (k >> 6) * 68 + (k & 63)] = v;
        }
#pragma unroll
        for (int half = 0; half < 2; half++) {
            int bG = lb + half * 8;                 // pair 0
            int lenG = g_lens[bG];
            float gv = 0.f;
            if (0 < lenG) {
                int tt0 = dir ? (lenG - 1) : 0;
                gv = __ldg(&Gd[((size_t)bG * TT + tt0) * G4H +
                               lg * HH + hcb + lch]);
            }
            sm[GS0_OFF + bG * 36 + lg * 8 + lch] = gv;
        }
    }
    __syncthreads();

    int s = 0, P = 0, buf = 0;
    for (;;) {
        int ns = s, nP = P + 1;
        if (nP == 2 || ns >= plen[nP]) { ns = s + 1; nP = 0; }
        bool have_next = (ns < maxlen);
        bool can_pre   = have_next && !(ns == s + 1 && P == 0);

        // ---- poll + prefetch next tick (overlaps the dot) ----
        float4 hpre[8];
        float  gpre[2] = {0.f, 0.f};
        if (can_pre) {
            if (ns > 0) {
                const unsigned* fp = &g_done[dir][ns - 1][nP];
                unsigned v;
                for (;;) {
                    asm volatile("ld.global.cg.u32 %0, [%1];"
                                 : "=r"(v) : "l"(fp));
                    if (v >= 64u) break;
                    __nanosleep(20);
                }
            }
            const float* hin = &g_hring[dir][ns & 3][nP * 16][0];
#pragma unroll
            for (int i = 0; i < 8; i++) {
                int idx = tid + 256 * i;
                hpre[i] = __ldcg((const float4*)&hin[idx * 4]);
            }
#pragma unroll
            for (int half = 0; half < 2; half++) {
                int bl = lb + half * 8;
                int bG = nP * 16 + bl;
                int lenG = g_lens[bG];
                if (ns < lenG) {
                    int tt = dir ? (lenG - 1 - ns) : ns;
                    gpre[half] = __ldg(&Gd[((size_t)bG * TT + tt) * G4H +
                                           lg * HH + hcb + lch]);
                }
            }
        }

        // ---- dot from h_s[buf]: 16 batches ----
        const float* hbase = sm + (buf ? H1_OFF : H0_OFF) + ks * 68;
        float* psts = part + w * 576 + lane;
#pragma unroll 2
        for (int b = 0; b < 16; b++) {
            const ulonglong2* hp = (const ulonglong2*)(hbase + b * 544);
            unsigned long long a0 = 0, a1 = 0;
#pragma unroll
            for (int jj = 0; jj < 16; jj++) {
                ulonglong2 h2 = hp[jj];
                FMA2(a0, h2.x, warr[jj].x);
                FMA2(a1, h2.y, warr[jj].y);
            }
            psts[b * 36] = sum2(a0) + sum2(a1);
        }
        __syncwarp();

        // ---- pointwise: thread (w, lane<16) for batch b = P*16+lane ----
        if (lane < 16) {
            int  b      = P * 16 + lane;
            bool active = (s < lenb2[P]);
            const float4* pp = (const float4*)(part + w * 576 + lane * 36);
            float4 s4 = pp[0];
#pragma unroll
            for (int jq = 1; jq < 8; jq++) {
                float4 t = pp[jq];
                s4.x += t.x; s4.y += t.y; s4.z += t.z; s4.w += t.w;
            }
            const float* gsm = sm + (buf ? GS1_OFF : GS0_OFF) + lane * 36;
            float gi = s4.x + gsm[0 * 8 + w] + bias[0];
            float gf = s4.y + gsm[1 * 8 + w] + bias[1];
            float gg = s4.z + gsm[2 * 8 + w] + bias[2];
            float go = s4.w + gsm[3 * 8 + w] + bias[3];
            float i_ = 1.f / (1.f + __expf(-gi));
            float f_ = 1.f / (1.f + __expf(-gf));
            float g_ = tanhf(gg);
            float o_ = 1.f / (1.f + __expf(-go));
            float cn = f_ * creg2[P] + i_ * g_;
            float hn = o_ * tanhf(cn);
            if (active) {
                creg2[P] = cn; hreg2[P] = hn;
                if (dir == 0) {
                    out[OUT_OFF + ((size_t)s * BB + b) * 1024 + hc] = hn;
                } else {
                    int tw = lenb2[P] - 1 - s;
                    out[OUT_OFF + ((size_t)tw * BB + b) * 1024 + 512 + hc] = hn;
                }
            }
            g_hring[dir][(s + 1) & 3][b][hc] = hreg2[P];
        }

        // ---- stage prefetched tick into the other buffer ----
        if (can_pre) {
            float* hdst = sm + (buf ? H0_OFF : H1_OFF);
#pragma unroll
            for (int i = 0; i < 8; i++) {
                int idx = tid + 256 * i;
                int b = idx >> 7;
                int k = (idx & 127) * 4;
                *(float4*)&hdst[b * 544 + (k >> 6) * 68 + (k & 63)] = hpre[i];
            }
            float* gdst = sm + (buf ? GS0_OFF : GS1_OFF);
            gdst[(lb + 0) * 36 + lg * 8 + lch] = gpre[0];
            gdst[(lb + 8) * 36 + lg * 8 + lch] = gpre[1];
        }

        // ---- release current tick (proven pattern) ----
        __syncthreads();
        if (tid == 0) {
            __threadfence();
            atomicAdd(&g_done[dir][s][P], 1u);
        }

        if (!have_next) break;

        // ---- fallback staging (single-pair tail: dep == current tick) ----
        if (!can_pre) {
            const unsigned* fp = &g_done[dir][ns - 1][nP];
            unsigned v;
            for (;;) {
                asm volatile("ld.global.cg.u32 %0, [%1];" : "=r"(v) : "l"(fp));
                if (v >= 64u) break;
                __nanosleep(20);
            }
            const float* hin = &g_hring[dir][ns & 3][nP * 16][0];
            float* hdst = sm + (buf ? H0_OFF : H1_OFF);
#pragma unroll
            for (int i = 0; i < 8; i++) {
                int idx = tid + 256 * i;
                float4 hv = __ldcg((const float4*)&hin[idx * 4]);
                int b = idx >> 7;
                int k = (idx & 127) * 4;
                *(float4*)&hdst[b * 544 + (k >> 6) * 68 + (k & 63)] = hv;
            }
            float* gdst = sm + (buf ? GS0_OFF : GS1_OFF);
#pragma unroll
            for (int half = 0; half < 2; half++) {
                int bl = lb + half * 8;
                int bG = nP * 16 + bl;
                int lenG = g_lens[bG];
                float gv = 0.f;
                if (ns < lenG) {
                    int tt = dir ? (lenG - 1 - ns) : ns;
                    gv = __ldg(&Gd[((size_t)bG * TT + tt) * G4H +
                                   lg * HH + hcb + lch]);
                }
                gdst[bl * 36 + lg * 8 + lch] = gv;
            }
            __syncthreads();
        }

        s = ns; P = nP; buf ^= 1;
    }

    // finals
    if (lane < 16) {
#pragma unroll
        for (int P2 = 0; P2 < 2; P2++) {
            int b = P2 * 16 + lane;
            out[HN_OFF + dir * 16384 + b * HH + hc] = hreg2[P2];
            out[CN_OFF + dir * 16384 + b * HH + hc] = creg2[P2];
        }
    }
}

// ---------------- launcher ----------------------------------------------
extern "C" void kernel_launch(void* const* d_in, const int* in_sizes, int n_in,
                              void* d_out, int out_size) {
    const float* cnn  = (const float*)d_in[0];
    const float* fcw  = (const float*)d_in[1];
    const float* fcb  = (const float*)d_in[2];
    const float* h0   = (const float*)d_in[3];
    const float* c0   = (const float*)d_in[4];
    const float* wihf = (const float*)d_in[5];
    const float* whhf = (const float*)d_in[6];
    const float* bihf = (const float*)d_in[7];
    const float* bhhf = (const float*)d_in[8];
    const float* wihb = (const float*)d_in[9];
    const float* whhb = (const float*)d_in[10];
    const float* bihb = (const float*)d_in[11];
    const float* bhhb = (const float*)d_in[12];
    const int* seq_lens = (const int*)d_in[13];
    const int* lookup   = (const int*)d_in[14];
    float* out = (float*)d_out;

    cudaFuncSetAttribute(k_scan, cudaFuncAttributeMaxDynamicSharedMemorySize,
                         SCAN_SMEM);

    k_reset<<<1, 256>>>(seq_lens, h0, out);
    k_zero<<<16384, 256>>>(out);
    k_prep<<<dim3(2048, 3), 256>>>(fcw, wihf, wihb);
    k_gemm1<<<dim3(8, 8, 32), 128>>>(cnn, fcb, lookup, out + X_OFF);
    k_gemm2<<<dim3(32, 256, 2), 128>>>(out + X_OFF);
    k_scan<<<128, 256, SCAN_SMEM>>>(c0, h0, whhf, whhb, bihf, bhhf, bihb,
                                    bhhb, out);
}

// round 15
// speedup vs baseline: 1.0906x; 1.0906x over previous
#include <cuda_runtime.h>
#include <cstdint>

// Problem dims
#define TT    512
#define BB    32
#define DD    512
#define HH    512
#define FEAT  2048
#define G4H   2048   // 4*H

// Output layout (fp32, tuple order: out, h_n, c_n, x, lens_s)
#define OUT_OFF  0
#define HN_OFF   16777216
#define CN_OFF   (16777216 + 32768)
#define X_OFF    (16777216 + 65536)
#define LENS_OFF (X_OFF + 8388608)

#define GSZ       (512*32*2048)        // per-direction G size (floats)
#define WCHUNKS   524288               // frag chunks per weight matrix
#define XCHUNKS   (4096 * 1024)        // x frag tiles: 32j * 8t0 * 16kt

// ---------------- device scratch ---------------------------------------
__device__ float    g_G[2 * GSZ];          // input-gate preactivations (268MB)
__device__ float    g_hring[2][4][BB][HH]; // h ring buffer, depth 4
__device__ unsigned g_done[2][TT][4];      // per (dir, step, group) counters
__device__ int      g_order[BB];
__device__ int      g_lens[BB];
__device__ uint4    g_wfc[WCHUNKS];        // fc_w   frag-layout (hi/lo tf32)
__device__ uint4    g_wih[2][WCHUNKS];     // w_ih_f / w_ih_b frag-layout
__device__ uint4    g_xfrag[XCHUNKS];      // x in B-frag layout (64MB)

// ---------------- helpers ----------------------------------------------
__device__ __forceinline__ uint32_t f2tf32(float v) {
    uint32_t r;
    asm("cvt.rna.tf32.f32 %0, %1;" : "=r"(r) : "f"(v));
    return r;
}

__device__ __forceinline__ void mma_tf32(float4& c, const uint4& a,
                                         uint32_t b0, uint32_t b1) {
    asm volatile(
        "mma.sync.aligned.m16n8k8.row.col.f32.tf32.tf32.f32 "
        "{%0,%1,%2,%3}, {%4,%5,%6,%7}, {%8,%9}, {%0,%1,%2,%3};"
        : "+f"(c.x), "+f"(c.y), "+f"(c.z), "+f"(c.w)
        : "r"(a.x), "r"(a.y), "r"(a.z), "r"(a.w), "r"(b0), "r"(b1));
}

#define FMA2(acc, a, b) \
    asm("fma.rn.f32x2 %0, %1, %2, %0;" : "+l"(acc) : "l"(a), "l"(b))

__device__ __forceinline__ float sum2(unsigned long long v) {
    float lo, hi;
    asm("mov.b64 {%0,%1}, %2;" : "=f"(lo), "=f"(hi) : "l"(v));
    return lo + hi;
}

__device__ __forceinline__ unsigned long long packf2(float a, float b) {
    unsigned long long u;
    asm("mov.b64 %0, {%1,%2};" : "=l"(u) : "f"(a), "f"(b));
    return u;
}

// ---------------- reset / sort kernel ----------------------------------
__global__ void k_reset(const int* __restrict__ seq_lens,
                        const float* __restrict__ h0,
                        float* __restrict__ out) {
    int tid = threadIdx.x;
    if (tid == 0) {
        unsigned used = 0u;
        for (int pos = 0; pos < BB; pos++) {
            int best = -1, bl = -1;
            for (int i = 0; i < BB; i++) {
                if (used & (1u << i)) continue;
                int L = seq_lens[i];
                if (L > bl) { bl = L; best = i; }
            }
            used |= 1u << best;
            g_order[pos] = best;
            g_lens[pos]  = bl;
            out[LENS_OFF + pos] = (float)bl;
        }
    }
    for (int i = tid; i < 2 * TT * 4; i += blockDim.x)
        ((unsigned*)g_done)[i] = 0u;
    for (int i = tid; i < 2 * 16384; i += blockDim.x) {
        int dir = i >> 14;
        int r   = i & 16383;
        g_hring[dir][0][r >> 9][r & 511] = h0[i];
    }
}

// ---------------- bulk zero of the `out` region -------------------------
__global__ void __launch_bounds__(256) k_zero(float* __restrict__ out) {
    size_t i = ((size_t)blockIdx.x * 256 + threadIdx.x) * 4;
    *(float4*)&out[OUT_OFF + i] = make_float4(0.f, 0.f, 0.f, 0.f);
}

// ---------------- weight pre-conversion to frag layout ------------------
__global__ void __launch_bounds__(256) k_prep(
    const float* __restrict__ fcw, const float* __restrict__ wihf,
    const float* __restrict__ wihb) {
    int z = blockIdx.y;
    const float* src = (z == 0) ? fcw : ((z == 1) ? wihf : wihb);
    uint4* dst = (z == 0) ? g_wfc : g_wih[z - 1];
    int K     = (z == 0) ? FEAT : DD;
    int nKtm1 = (z == 0) ? 63 : 15;
    int nKtsh = (z == 0) ? 6 : 4;

    int c    = blockIdx.x * 256 + threadIdx.x;
    int lane = c & 31;
    int hl   = (c >> 5) & 1;
    int s    = (c >> 6) & 3;
    int q    = (c >> 8) & 3;
    int tile = c >> 10;
    int qt   = tile & nKtm1;
    int r64  = tile >> nKtsh;
    int g    = lane >> 2, tg = lane & 3;
    int m0   = r64 * 64 + s * 16;
    int kk   = qt * 32 + q * 8 + tg;

    float v0 = src[(size_t)(m0 + g)     * K + kk];
    float v1 = src[(size_t)(m0 + g + 8) * K + kk];
    float v2 = src[(size_t)(m0 + g)     * K + kk + 4];
    float v3 = src[(size_t)(m0 + g + 8) * K + kk + 4];
    uint4 o;
    if (hl == 0) {
        o.x = f2tf32(v0); o.y = f2tf32(v1); o.z = f2tf32(v2); o.w = f2tf32(v3);
    } else {
        o.x = f2tf32(v0 - __uint_as_float(f2tf32(v0)));
        o.y = f2tf32(v1 - __uint_as_float(f2tf32(v1)));
        o.z = f2tf32(v2 - __uint_as_float(f2tf32(v2)));
        o.w = f2tf32(v3 - __uint_as_float(f2tf32(v3)));
    }
    dst[c] = o;
}

// ---------------- x pre-conversion to B-frag layout ---------------------
// Chunk c: tile = c>>10 = (j*8 + t0i)*16 + kt ; rem = c&1023:
//   q = rem>>8, r = (rem>>2)&63, sw = rem&3, t2 = sw ^ ((r&3)^((r>>2)&3))
// chunk = {hi(x[t][k]), hi(x[t][k+4]), lo(x[t][k]), lo(x[t][k+4])},
//   t = t0i*64 + r, k = kt*32 + q*8 + t2  — matches sts_b_convert layout.
__global__ void __launch_bounds__(256) k_prepx(const float* __restrict__ x) {
    int c    = blockIdx.x * 256 + threadIdx.x;
    int tile = c >> 10;
    int rem  = c & 1023;
    int q  = rem >> 8;
    int r  = (rem >> 2) & 63;
    int sw = rem & 3;
    int xr = (r & 3) ^ ((r >> 2) & 3);
    int t2 = sw ^ xr;
    int kt  = tile & 15;
    int t0i = (tile >> 4) & 7;
    int j   = tile >> 7;
    int t   = t0i * 64 + r;
    int k0  = kt * 32 + q * 8;
    const float* row = &x[((size_t)t * BB + j) * DD];
    float v0 = row[k0 + t2];
    float v1 = row[k0 + t2 + 4];
    uint4 o;
    o.x = f2tf32(v0);
    o.y = f2tf32(v1);
    o.z = f2tf32(v0 - __uint_as_float(o.x));
    o.w = f2tf32(v1 - __uint_as_float(o.y));
    g_xfrag[c] = o;
}

// ================= MMA GEMMs (A = weights frag-global) =================
__device__ __forceinline__ void sts_b_convert(uint4* Bsm, const float4* braw,
                                              int r, int qp) {
    int xr = (r & 3) ^ ((r >> 2) & 3);
#pragma unroll
    for (int oo = 0; oo < 2; oo++) {
        float f[8];
        f[0] = braw[oo*2].x;   f[1] = braw[oo*2].y;
        f[2] = braw[oo*2].z;   f[3] = braw[oo*2].w;
        f[4] = braw[oo*2+1].x; f[5] = braw[oo*2+1].y;
        f[6] = braw[oo*2+1].z; f[7] = braw[oo*2+1].w;
        uint32_t hi[8], lo[8];
#pragma unroll
        for (int p = 0; p < 8; p++) {
            hi[p] = f2tf32(f[p]);
            lo[p] = f2tf32(f[p] - __uint_as_float(hi[p]));
        }
        int q = qp * 2 + oo;
        int sbase = q * 256 + r * 4;
#pragma unroll
        for (int t2 = 0; t2 < 4; t2++) {
            uint4 ch;
            ch.x = hi[t2]; ch.y = hi[t2 + 4];
            ch.z = lo[t2]; ch.w = lo[t2 + 4];
            Bsm[sbase + (t2 ^ xr)] = ch;
        }
    }
}

__device__ __forceinline__ void mma_ktile(const uint4* As, const uint4* Bsm,
                                          float4 c[2][4], int wm, int wn,
                                          int lane, int g, int tg) {
#pragma unroll
    for (int q = 0; q < 4; q++) {
        uint4 ah[2], al[2], bq[4];
#pragma unroll
        for (int mi = 0; mi < 2; mi++) {
            int s = wm * 2 + mi;
            ah[mi] = As[((q * 4 + s) * 2 + 0) * 32 + lane];
            al[mi] = As[((q * 4 + s) * 2 + 1) * 32 + lane];
        }
#pragma unroll
        for (int ni = 0; ni < 4; ni++) {
            int rr = wn * 32 + ni * 8 + g;
            int sw = tg ^ (rr & 3) ^ ((rr >> 2) & 3);
            bq[ni] = Bsm[q * 256 + rr * 4 + sw];
        }
#pragma unroll
        for (int mi = 0; mi < 2; mi++)
#pragma unroll
            for (int ni = 0; ni < 4; ni++) {
                mma_tf32(c[mi][ni], ah[mi], bq[ni].x, bq[ni].y);
                mma_tf32(c[mi][ni], ah[mi], bq[ni].z, bq[ni].w);
                mma_tf32(c[mi][ni], al[mi], bq[ni].x, bq[ni].y);
            }
    }
}

// GEMM1: x[t,j,ch] = mask * (cnn[lookup[order[j],t]] @ fc_w^T + fc_b)[ch]
__global__ void __launch_bounds__(128) k_gemm1(
    const float* __restrict__ cnn, const float* __restrict__ fcb,
    const int* __restrict__ lookup, float* __restrict__ xout) {
    __shared__ uint4 As[1024];
    __shared__ uint4 Bsm[1024];
    __shared__ int   simg[64];

    int j   = blockIdx.z;
    int t0  = blockIdx.y * 64;
    int m0  = blockIdx.x * 64;
    int tid = threadIdx.x;
    int len = g_lens[j];

    if (t0 >= len) {
        for (int i = tid; i < 1024; i += 128) {
            int r  = i >> 4;
            int cc = (i & 15) * 4;
            int t  = t0 + r;
            *(float4*)&xout[((size_t)t * BB + j) * DD + m0 + cc] =
                make_float4(0.f, 0.f, 0.f, 0.f);
        }
        return;
    }
    if (tid < 64) simg[tid] = lookup[g_order[j] * TT + t0 + tid];
    __syncthreads();

    int lane = tid & 31;
    int w    = tid >> 5;
    int wm   = w >> 1, wn = w & 1;
    int g    = lane >> 2, tg = lane & 3;
    int r    = tid >> 1, qp = tid & 1;
    size_t brow = (size_t)simg[r] * FEAT;

    float4 c[2][4];
#pragma unroll
    for (int mi = 0; mi < 2; mi++)
#pragma unroll
        for (int ni = 0; ni < 4; ni++) c[mi][ni] = make_float4(0.f,0.f,0.f,0.f);

    uint4  areg[8];
    float4 braw[4];
    {
        const uint4* at = g_wfc + ((size_t)blockIdx.x * 64 + 0) * 1024;
#pragma unroll
        for (int u = 0; u < 8; u++) areg[u] = at[tid + 128 * u];
        int kb = qp * 16;
#pragma unroll
        for (int u = 0; u < 4; u++)
            braw[u] = *(const float4*)&cnn[brow + kb + u * 4];
    }

    for (int kt = 0; kt < 64; kt++) {
        __syncthreads();
#pragma unroll
        for (int u = 0; u < 8; u++) As[tid + 128 * u] = areg[u];
        sts_b_convert(Bsm, braw, r, qp);
        __syncthreads();
        if (kt + 1 < 64) {
            const uint4* at = g_wfc + ((size_t)blockIdx.x * 64 + kt + 1) * 1024;
#pragma unroll
            for (int u = 0; u < 8; u++) areg[u] = at[tid + 128 * u];
            int kb = (kt + 1) * 32 + qp * 16;
#pragma unroll
            for (int u = 0; u < 4; u++)
                braw[u] = *(const float4*)&cnn[brow + kb + u * 4];
        }
        mma_ktile(As, Bsm, c, wm, wn, lane, g, tg);
    }

#pragma unroll
    for (int mi = 0; mi < 2; mi++) {
        int ch  = m0 + wm * 32 + mi * 16 + g;
        float b0 = fcb[ch], b8 = fcb[ch + 8];
#pragma unroll
        for (int ni = 0; ni < 4; ni++) {
            int tA = t0 + wn * 32 + ni * 8 + 2 * tg;
            bool v0 = (tA < len), v1 = (tA + 1 < len);
            size_t r0o = ((size_t)tA * BB + j) * DD;
            size_t r1o = ((size_t)(tA + 1) * BB + j) * DD;
            xout[r0o + ch]     = v0 ? c[mi][ni].x + b0 : 0.f;
            xout[r1o + ch]     = v1 ? c[mi][ni].y + b0 : 0.f;
            xout[r0o + ch + 8] = v0 ? c[mi][ni].z + b8 : 0.f;
            xout[r1o + ch + 8] = v1 ? c[mi][ni].w + b8 : 0.f;
        }
    }
}

// GEMM2: G[dir][j,t,ch] = x[t,j,:] @ w_ih[dir]^T — B from g_xfrag (no cvt)
__global__ void __launch_bounds__(128) k_gemm2() {
    __shared__ uint4 As[1024];
    __shared__ uint4 Bsm[1024];

    int dir = blockIdx.z;
    int j   = blockIdx.y >> 3;
    int t0i = blockIdx.y & 7;
    int t0  = t0i * 64;
    int m0  = blockIdx.x * 64;
    int tid = threadIdx.x;
    int len = g_lens[j];
    if (t0 >= len) return;

    int lane = tid & 31;
    int w    = tid >> 5;
    int wm   = w >> 1, wn = w & 1;
    int g    = lane >> 2, tg = lane & 3;

    float4 c[2][4];
#pragma unroll
    for (int mi = 0; mi < 2; mi++)
#pragma unroll
        for (int ni = 0; ni < 4; ni++) c[mi][ni] = make_float4(0.f,0.f,0.f,0.f);

    const uint4* wbase = g_wih[dir];
    const uint4* xbase = g_xfrag + ((size_t)((j * 8 + t0i) * 16)) * 1024;
    uint4 areg[8], breg[8];
    {
        const uint4* at = wbase + ((size_t)blockIdx.x * 16 + 0) * 1024;
#pragma unroll
        for (int u = 0; u < 8; u++) areg[u] = at[tid + 128 * u];
#pragma unroll
        for (int u = 0; u < 8; u++) breg[u] = xbase[tid + 128 * u];
    }

    for (int kt = 0; kt < 16; kt++) {
        __syncthreads();
#pragma unroll
        for (int u = 0; u < 8; u++) As[tid + 128 * u] = areg[u];
#pragma unroll
        for (int u = 0; u < 8; u++) Bsm[tid + 128 * u] = breg[u];
        __syncthreads();
        if (kt + 1 < 16) {
            const uint4* at = wbase + ((size_t)blockIdx.x * 16 + kt + 1) * 1024;
            const uint4* bt = xbase + (size_t)(kt + 1) * 1024;
#pragma unroll
            for (int u = 0; u < 8; u++) areg[u] = at[tid + 128 * u];
#pragma unroll
            for (int u = 0; u < 8; u++) breg[u] = bt[tid + 128 * u];
        }
        mma_ktile(As, Bsm, c, wm, wn, lane, g, tg);
    }

    float* Gd = g_G + (size_t)dir * GSZ;
#pragma unroll
    for (int mi = 0; mi < 2; mi++) {
        int ch = m0 + wm * 32 + mi * 16 + g;
#pragma unroll
        for (int ni = 0; ni < 4; ni++) {
            int tA = t0 + wn * 32 + ni * 8 + 2 * tg;
            size_t r0o = ((size_t)j * TT + tA) * G4H;
            size_t r1o = ((size_t)j * TT + tA + 1) * G4H;
            Gd[r0o + ch]     = c[mi][ni].x;
            Gd[r1o + ch]     = c[mi][ni].y;
            Gd[r0o + ch + 8] = c[mi][ni].z;
            Gd[r1o + ch + 8] = c[mi][ni].w;
        }
    }
}

// ---------------- persistent scan kernel (v7, R13-proven) ---------------
__global__ void __launch_bounds__(256, 1) k_scan(
    const float* __restrict__ c0, const float* __restrict__ h0,
    const float* __restrict__ whhf, const float* __restrict__ whhb,
    const float* __restrict__ bihf, const float* __restrict__ bhhf,
    const float* __restrict__ bihb, const float* __restrict__ bhhb,
    float* __restrict__ out) {
    __shared__ float h_s[2][8 * 544];
    __shared__ float g_sm[2][8 * 36];
    __shared__ float part[8 * 288];

    int bid  = blockIdx.x;
    int dir  = bid >> 6;
    int ctad = bid & 63;
    int hcb  = ctad * 8;
    int tid  = threadIdx.x;
    int w    = tid >> 5;
    int lane = tid & 31;
    int g4   = lane & 3;
    int ks   = lane >> 2;
    int hc   = hcb + w;

    const float* whh = dir ? whhb : whhf;
    ulonglong2 warr[16];
    {
        const float* wrow = whh + (size_t)(g4 * HH + hc) * HH + ks * 64;
#pragma unroll
        for (int i = 0; i < 16; i++) {
            float4 v = *(const float4*)(wrow + i * 4);
            warr[i].x = packf2(v.x, v.y);
            warr[i].y = packf2(v.z, v.w);
        }
    }
    float bias[4];
    {
        const float* bih = dir ? bihb : bihf;
        const float* bhh = dir ? bhhb : bhhf;
#pragma unroll
        for (int q = 0; q < 4; q++)
            bias[q] = bih[q * HH + hc] + bhh[q * HH + hc];
    }

    float creg[4], hreg[4];
    int   lenp[4];
    if (lane < 8) {
#pragma unroll
        for (int g = 0; g < 4; g++) {
            int b = g * 8 + lane;
            lenp[g] = g_lens[b];
            creg[g] = c0[dir * 16384 + b * HH + hc];
            hreg[g] = h0[dir * 16384 + b * HH + hc];
        }
    }

    int lb  = tid >> 5;
    int lg  = (tid & 31) >> 3;
    int lch = tid & 7;
    const float* Gd = g_G + (size_t)dir * GSZ;
    int lenG4[4];
#pragma unroll
    for (int g = 0; g < 4; g++) lenG4[g] = g_lens[g * 8 + lb];

    int glen[4];
#pragma unroll
    for (int g = 0; g < 4; g++) glen[g] = g_lens[g * 8];
    int maxlen = glen[0];

    {
        const float* hin = &g_hring[dir][0][0][0];
#pragma unroll
        for (int i = 0; i < 4; i++) {
            int idx = tid + 256 * i;
            float4 v = __ldcg((const float4*)&hin[idx * 4]);
            int b = idx >> 7;
            int k = (idx & 127) * 4;
            *(float4*)&h_s[0][b * 544 + (k >> 6) * 68 + (k & 63)] = v;
        }
        float gv = 0.f;
        if (0 < lenG4[0]) {
            int tt0 = dir ? (lenG4[0] - 1) : 0;
            gv = __ldg(&Gd[((size_t)lb * TT + tt0) * G4H + lg * HH + hcb + lch]);
        }
        g_sm[0][lb * 36 + lg * 8 + lch] = gv;
    }
    __syncthreads();

    int s = 0, g = 0, buf = 0;
    for (;;) {
        int ns = s, ng = g + 1;
        if (ng == 4 || ns >= glen[ng]) { ns = s + 1; ng = 0; }
        bool have_next = (ns < maxlen);
        bool can_pre   = have_next && !(ns == s + 1 && g == 0);

        float4 hpre[4];
        float  gpre = 0.f;
        if (can_pre) {
            if (ns > 0) {
                const unsigned* fp = &g_done[dir][ns - 1][ng];
                unsigned v;
                for (;;) {
                    asm volatile("ld.global.cg.u32 %0, [%1];"
                                 : "=r"(v) : "l"(fp));
                    if (v >= 64u) break;
                    __nanosleep(20);
                }
            }
            const float* hin = &g_hring[dir][ns & 3][ng * 8][0];
#pragma unroll
            for (int i = 0; i < 4; i++) {
                int idx = tid + 256 * i;
                hpre[i] = __ldcg((const float4*)&hin[idx * 4]);
            }
            if (ns < lenG4[ng]) {
                int bG = ng * 8 + lb;
                int tt = dir ? (lenG4[ng] - 1 - ns) : ns;
                gpre = __ldg(&Gd[((size_t)bG * TT + tt) * G4H +
                                 lg * HH + hcb + lch]);
            }
        }

        const float* hbase = &h_s[buf][0] + ks * 68;
        float* psts = part + w * 288 + lane;
#pragma unroll 2
        for (int b = 0; b < 8; b++) {
            const ulonglong2* hp = (const ulonglong2*)(hbase + b * 544);
            unsigned long long a0 = 0, a1 = 0;
#pragma unroll
            for (int jj = 0; jj < 16; jj++) {
                ulonglong2 h2 = hp[jj];
                FMA2(a0, h2.x, warr[jj].x);
                FMA2(a1, h2.y, warr[jj].y);
            }
            psts[b * 36] = sum2(a0) + sum2(a1);
        }
        __syncwarp();

        if (lane < 8) {
            int  b      = g * 8 + lane;
            bool active = (s < lenp[g]);
            const float4* pp = (const float4*)(part + w * 288 + lane * 36);
            float4 s4 = pp[0];
#pragma unroll
            for (int jq = 1; jq < 8; jq++) {
                float4 t = pp[jq];
                s4.x += t.x; s4.y += t.y; s4.z += t.z; s4.w += t.w;
            }
            float gi = s4.x + g_sm[buf][lane * 36 + 0 * 8 + w] + bias[0];
            float gf = s4.y + g_sm[buf][lane * 36 + 1 * 8 + w] + bias[1];
            float gg = s4.z + g_sm[buf][lane * 36 + 2 * 8 + w] + bias[2];
            float go = s4.w + g_sm[buf][lane * 36 + 3 * 8 + w] + bias[3];
            float i_ = 1.f / (1.f + __expf(-gi));
            float f_ = 1.f / (1.f + __expf(-gf));
            float g_ = tanhf(gg);
            float o_ = 1.f / (1.f + __expf(-go));
            float cn = f_ * creg[g] + i_ * g_;
            float hn = o_ * tanhf(cn);
            if (active) {
                creg[g] = cn; hreg[g] = hn;
                if (dir == 0) {
                    out[OUT_OFF + ((size_t)s * BB + b) * 1024 + hc] = hn;
                } else {
                    int tw = lenp[g] - 1 - s;
                    out[OUT_OFF + ((size_t)tw * BB + b) * 1024 + 512 + hc] = hn;
                }
            }
            g_hring[dir][(s + 1) & 3][b][hc] = hreg[g];
        }

        if (can_pre) {
#pragma unroll
            for (int i = 0; i < 4; i++) {
                int idx = tid + 256 * i;
                int b = idx >> 7;
                int k = (idx & 127) * 4;
                *(float4*)&h_s[buf ^ 1][b * 544 + (k >> 6) * 68 + (k & 63)]
                    = hpre[i];
            }
            g_sm[buf ^ 1][lb * 36 + lg * 8 + lch] = gpre;
        }

        __syncthreads();
        if (tid == 0) {
            __threadfence();
            atomicAdd(&g_done[dir][s][g], 1u);
        }

        if (!have_next) break;

        if (!can_pre) {
            const unsigned* fp = &g_done[dir][ns - 1][ng];
            unsigned v;
            for (;;) {
                asm volatile("ld.global.cg.u32 %0, [%1];" : "=r"(v) : "l"(fp));
                if (v >= 64u) break;
                __nanosleep(20);
            }
            const float* hin = &g_hring[dir][ns & 3][ng * 8][0];
#pragma unroll
            for (int i = 0; i < 4; i++) {
                int idx = tid + 256 * i;
                float4 hv = __ldcg((const float4*)&hin[idx * 4]);
                int b = idx >> 7;
                int k = (idx & 127) * 4;
                *(float4*)&h_s[buf ^ 1][b * 544 + (k >> 6) * 68 + (k & 63)]
                    = hv;
            }
            float gv = 0.f;
            if (ns < lenG4[ng]) {
                int bG = ng * 8 + lb;
                int tt = dir ? (lenG4[ng] - 1 - ns) : ns;
                gv = __ldg(&Gd[((size_t)bG * TT + tt) * G4H +
                               lg * HH + hcb + lch]);
            }
            g_sm[buf ^ 1][lb * 36 + lg * 8 + lch] = gv;
            __syncthreads();
        }

        s = ns; g = ng; buf ^= 1;
    }

    if (lane < 8) {
#pragma unroll
        for (int g = 0; g < 4; g++) {
            int b = g * 8 + lane;
            out[HN_OFF + dir * 16384 + b * HH + hc] = hreg[g];
            out[CN_OFF + dir * 16384 + b * HH + hc] = creg[g];
        }
    }
}

// ---------------- launcher ----------------------------------------------
extern "C" void kernel_launch(void* const* d_in, const int* in_sizes, int n_in,
                              void* d_out, int out_size) {
    const float* cnn  = (const float*)d_in[0];
    const float* fcw  = (const float*)d_in[1];
    const float* fcb  = (const float*)d_in[2];
    const float* h0   = (const float*)d_in[3];
    const float* c0   = (const float*)d_in[4];
    const float* wihf = (const float*)d_in[5];
    const float* whhf = (const float*)d_in[6];
    const float* bihf = (const float*)d_in[7];
    const float* bhhf = (const float*)d_in[8];
    const float* wihb = (const float*)d_in[9];
    const float* whhb = (const float*)d_in[10];
    const float* bihb = (const float*)d_in[11];
    const float* bhhb = (const float*)d_in[12];
    const int* seq_lens = (const int*)d_in[13];
    const int* lookup   = (const int*)d_in[14];
    float* out = (float*)d_out;

    k_reset<<<1, 256>>>(seq_lens, h0, out);
    k_zero<<<16384, 256>>>(out);
    k_prep<<<dim3(2048, 3), 256>>>(fcw, wihf, wihb);
    k_gemm1<<<dim3(8, 8, 32), 128>>>(cnn, fcb, lookup, out + X_OFF);
    k_prepx<<<16384, 256>>>(out + X_OFF);
    k_gemm2<<<dim3(32, 256, 2), 128>>>();
    k_scan<<<128, 256>>>(c0, h0, whhf, whhb, bihf, bhhf, bihb, bhhb, out);
}

// round 16
// speedup vs baseline: 1.1179x; 1.0250x over previous
#include <cuda_runtime.h>
#include <cstdint>

// Problem dims
#define TT    512
#define BB    32
#define DD    512
#define HH    512
#define FEAT  2048
#define G4H   2048   // 4*H

// Output layout (fp32, tuple order: out, h_n, c_n, x, lens_s)
#define OUT_OFF  0
#define HN_OFF   16777216
#define CN_OFF   (16777216 + 32768)
#define X_OFF    (16777216 + 65536)
#define LENS_OFF (X_OFF + 8388608)

#define GSZ       (512*32*2048)        // per-direction G size (floats)
#define WCHUNKS   524288               // frag chunks per weight matrix
#define XCHUNKS   (4096 * 1024)        // x frag tiles: 32j * 8t0 * 16kt
#define X1CHUNKS  (16384 * 1024)       // cnn frag tiles: 32j * 8t0 * 64kt

// ---------------- device scratch ---------------------------------------
__device__ float    g_G[2 * GSZ];          // input-gate preactivations (268MB)
__device__ float    g_hring[2][4][BB][HH]; // h ring buffer, depth 4
__device__ unsigned g_done[2][TT][4];      // per (dir, step, group) counters
__device__ int      g_order[BB];
__device__ int      g_lens[BB];
__device__ uint4    g_wfc[WCHUNKS];        // fc_w   frag-layout (hi/lo tf32)
__device__ uint4    g_wih[2][WCHUNKS];     // w_ih_f / w_ih_b frag-layout
__device__ uint4    g_xfrag[XCHUNKS];      // x in B-frag layout (64MB)
__device__ uint4    g_x1frag[X1CHUNKS];    // gathered cnn in B-frag (256MB)

// ---------------- helpers ----------------------------------------------
__device__ __forceinline__ uint32_t f2tf32(float v) {
    uint32_t r;
    asm("cvt.rna.tf32.f32 %0, %1;" : "=r"(r) : "f"(v));
    return r;
}

__device__ __forceinline__ void mma_tf32(float4& c, const uint4& a,
                                         uint32_t b0, uint32_t b1) {
    asm volatile(
        "mma.sync.aligned.m16n8k8.row.col.f32.tf32.tf32.f32 "
        "{%0,%1,%2,%3}, {%4,%5,%6,%7}, {%8,%9}, {%0,%1,%2,%3};"
        : "+f"(c.x), "+f"(c.y), "+f"(c.z), "+f"(c.w)
        : "r"(a.x), "r"(a.y), "r"(a.z), "r"(a.w), "r"(b0), "r"(b1));
}

#define FMA2(acc, a, b) \
    asm("fma.rn.f32x2 %0, %1, %2, %0;" : "+l"(acc) : "l"(a), "l"(b))

__device__ __forceinline__ float sum2(unsigned long long v) {
    float lo, hi;
    asm("mov.b64 {%0,%1}, %2;" : "=f"(lo), "=f"(hi) : "l"(v));
    return lo + hi;
}

__device__ __forceinline__ unsigned long long packf2(float a, float b) {
    unsigned long long u;
    asm("mov.b64 %0, {%1,%2};" : "=l"(u) : "f"(a), "f"(b));
    return u;
}

__device__ __forceinline__ float fast_sigmoid(float x) {
    return __fdividef(1.f, 1.f + __expf(-x));
}
__device__ __forceinline__ float fast_tanh(float x) {
    float t = __expf(2.f * fabsf(x));
    float r = 1.f - __fdividef(2.f, t + 1.f);
    return copysignf(r, x);
}

// ---------------- reset / sort kernel ----------------------------------
__global__ void k_reset(const int* __restrict__ seq_lens,
                        const float* __restrict__ h0,
                        float* __restrict__ out) {
    int tid = threadIdx.x;
    if (tid == 0) {
        unsigned used = 0u;
        for (int pos = 0; pos < BB; pos++) {
            int best = -1, bl = -1;
            for (int i = 0; i < BB; i++) {
                if (used & (1u << i)) continue;
                int L = seq_lens[i];
                if (L > bl) { bl = L; best = i; }
            }
            used |= 1u << best;
            g_order[pos] = best;
            g_lens[pos]  = bl;
            out[LENS_OFF + pos] = (float)bl;
        }
    }
    for (int i = tid; i < 2 * TT * 4; i += blockDim.x)
        ((unsigned*)g_done)[i] = 0u;
    for (int i = tid; i < 2 * 16384; i += blockDim.x) {
        int dir = i >> 14;
        int r   = i & 16383;
        g_hring[dir][0][r >> 9][r & 511] = h0[i];
    }
}

// ---------------- bulk zero of the `out` region -------------------------
__global__ void __launch_bounds__(256) k_zero(float* __restrict__ out) {
    size_t i = ((size_t)blockIdx.x * 256 + threadIdx.x) * 4;
    *(float4*)&out[OUT_OFF + i] = make_float4(0.f, 0.f, 0.f, 0.f);
}

// ---------------- weight pre-conversion to frag layout ------------------
__global__ void __launch_bounds__(256) k_prep(
    const float* __restrict__ fcw, const float* __restrict__ wihf,
    const float* __restrict__ wihb) {
    int z = blockIdx.y;
    const float* src = (z == 0) ? fcw : ((z == 1) ? wihf : wihb);
    uint4* dst = (z == 0) ? g_wfc : g_wih[z - 1];
    int K     = (z == 0) ? FEAT : DD;
    int nKtm1 = (z == 0) ? 63 : 15;
    int nKtsh = (z == 0) ? 6 : 4;

    int c    = blockIdx.x * 256 + threadIdx.x;
    int lane = c & 31;
    int hl   = (c >> 5) & 1;
    int s    = (c >> 6) & 3;
    int q    = (c >> 8) & 3;
    int tile = c >> 10;
    int qt   = tile & nKtm1;
    int r64  = tile >> nKtsh;
    int g    = lane >> 2, tg = lane & 3;
    int m0   = r64 * 64 + s * 16;
    int kk   = qt * 32 + q * 8 + tg;

    float v0 = src[(size_t)(m0 + g)     * K + kk];
    float v1 = src[(size_t)(m0 + g + 8) * K + kk];
    float v2 = src[(size_t)(m0 + g)     * K + kk + 4];
    float v3 = src[(size_t)(m0 + g + 8) * K + kk + 4];
    uint4 o;
    if (hl == 0) {
        o.x = f2tf32(v0); o.y = f2tf32(v1); o.z = f2tf32(v2); o.w = f2tf32(v3);
    } else {
        o.x = f2tf32(v0 - __uint_as_float(f2tf32(v0)));
        o.y = f2tf32(v1 - __uint_as_float(f2tf32(v1)));
        o.z = f2tf32(v2 - __uint_as_float(f2tf32(v2)));
        o.w = f2tf32(v3 - __uint_as_float(f2tf32(v3)));
    }
    dst[c] = o;
}

// ---------------- x pre-conversion to B-frag layout (GEMM2 B) -----------
__global__ void __launch_bounds__(256) k_prepx(const float* __restrict__ x) {
    int c    = blockIdx.x * 256 + threadIdx.x;
    int tile = c >> 10;
    int rem  = c & 1023;
    int q  = rem >> 8;
    int r  = (rem >> 2) & 63;
    int sw = rem & 3;
    int xr = (r & 3) ^ ((r >> 2) & 3);
    int t2 = sw ^ xr;
    int kt  = tile & 15;
    int t0i = (tile >> 4) & 7;
    int j   = tile >> 7;
    int t   = t0i * 64 + r;
    int k0  = kt * 32 + q * 8;
    const float* row = &x[((size_t)t * BB + j) * DD];
    float v0 = row[k0 + t2];
    float v1 = row[k0 + t2 + 4];
    uint4 o;
    o.x = f2tf32(v0);
    o.y = f2tf32(v1);
    o.z = f2tf32(v0 - __uint_as_float(o.x));
    o.w = f2tf32(v1 - __uint_as_float(o.y));
    g_xfrag[c] = o;
}

// ---------------- gathered-cnn pre-conversion (GEMM1 B) -----------------
__global__ void __launch_bounds__(256) k_prepx1(
    const float* __restrict__ cnn, const int* __restrict__ lookup) {
    int c    = blockIdx.x * 256 + threadIdx.x;
    int tile = c >> 10;               // (j*8 + t0i)*64 + kt
    int rem  = c & 1023;
    int q  = rem >> 8;
    int r  = (rem >> 2) & 63;
    int sw = rem & 3;
    int xr = (r & 3) ^ ((r >> 2) & 3);
    int t2 = sw ^ xr;
    int kt  = tile & 63;
    int t0i = (tile >> 6) & 7;
    int j   = tile >> 9;
    int len = g_lens[j];
    if (t0i * 64 >= len) return;      // fully masked tile: gemm1 skips it
    int t   = t0i * 64 + r;
    int img = lookup[g_order[j] * TT + t];
    int k0  = kt * 32 + q * 8;
    const float* row = &cnn[(size_t)img * FEAT + k0];
    float v0 = row[t2];
    float v1 = row[t2 + 4];
    uint4 o;
    o.x = f2tf32(v0);
    o.y = f2tf32(v1);
    o.z = f2tf32(v0 - __uint_as_float(o.x));
    o.w = f2tf32(v1 - __uint_as_float(o.y));
    g_x1frag[c] = o;
}

// ================= MMA GEMMs (both operands frag-global) ===============
__device__ __forceinline__ void mma_ktile(const uint4* As, const uint4* Bsm,
                                          float4 c[2][4], int wm, int wn,
                                          int lane, int g, int tg) {
#pragma unroll
    for (int q = 0; q < 4; q++) {
        uint4 ah[2], al[2], bq[4];
#pragma unroll
        for (int mi = 0; mi < 2; mi++) {
            int s = wm * 2 + mi;
            ah[mi] = As[((q * 4 + s) * 2 + 0) * 32 + lane];
            al[mi] = As[((q * 4 + s) * 2 + 1) * 32 + lane];
        }
#pragma unroll
        for (int ni = 0; ni < 4; ni++) {
            int rr = wn * 32 + ni * 8 + g;
            int sw = tg ^ (rr & 3) ^ ((rr >> 2) & 3);
            bq[ni] = Bsm[q * 256 + rr * 4 + sw];
        }
#pragma unroll
        for (int mi = 0; mi < 2; mi++)
#pragma unroll
            for (int ni = 0; ni < 4; ni++) {
                mma_tf32(c[mi][ni], ah[mi], bq[ni].x, bq[ni].y);
                mma_tf32(c[mi][ni], ah[mi], bq[ni].z, bq[ni].w);
                mma_tf32(c[mi][ni], al[mi], bq[ni].x, bq[ni].y);
            }
    }
}

// GEMM1: x[t,j,ch] = mask * (cnn[lookup[order[j],t]] @ fc_w^T + fc_b)[ch]
__global__ void __launch_bounds__(128) k_gemm1(
    const float* __restrict__ fcb, float* __restrict__ xout) {
    __shared__ uint4 As[1024];
    __shared__ uint4 Bsm[1024];

    int j   = blockIdx.z;
    int t0i = blockIdx.y;
    int t0  = t0i * 64;
    int m0  = blockIdx.x * 64;
    int tid = threadIdx.x;
    int len = g_lens[j];

    if (t0 >= len) {
        for (int i = tid; i < 1024; i += 128) {
            int r  = i >> 4;
            int cc = (i & 15) * 4;
            int t  = t0 + r;
            *(float4*)&xout[((size_t)t * BB + j) * DD + m0 + cc] =
                make_float4(0.f, 0.f, 0.f, 0.f);
        }
        return;
    }

    int lane = tid & 31;
    int w    = tid >> 5;
    int wm   = w >> 1, wn = w & 1;
    int g    = lane >> 2, tg = lane & 3;

    float4 c[2][4];
#pragma unroll
    for (int mi = 0; mi < 2; mi++)
#pragma unroll
        for (int ni = 0; ni < 4; ni++) c[mi][ni] = make_float4(0.f,0.f,0.f,0.f);

    const uint4* xbase = g_x1frag + ((size_t)((j * 8 + t0i) * 64)) * 1024;
    uint4 areg[8], breg[8];
    {
        const uint4* at = g_wfc + ((size_t)blockIdx.x * 64 + 0) * 1024;
#pragma unroll
        for (int u = 0; u < 8; u++) areg[u] = at[tid + 128 * u];
#pragma unroll
        for (int u = 0; u < 8; u++) breg[u] = xbase[tid + 128 * u];
    }

    for (int kt = 0; kt < 64; kt++) {
        __syncthreads();
#pragma unroll
        for (int u = 0; u < 8; u++) As[tid + 128 * u] = areg[u];
#pragma unroll
        for (int u = 0; u < 8; u++) Bsm[tid + 128 * u] = breg[u];
        __syncthreads();
        if (kt + 1 < 64) {
            const uint4* at = g_wfc + ((size_t)blockIdx.x * 64 + kt + 1) * 1024;
            const uint4* bt = xbase + (size_t)(kt + 1) * 1024;
#pragma unroll
            for (int u = 0; u < 8; u++) areg[u] = at[tid + 128 * u];
#pragma unroll
            for (int u = 0; u < 8; u++) breg[u] = bt[tid + 128 * u];
        }
        mma_ktile(As, Bsm, c, wm, wn, lane, g, tg);
    }

#pragma unroll
    for (int mi = 0; mi < 2; mi++) {
        int ch  = m0 + wm * 32 + mi * 16 + g;
        float b0 = fcb[ch], b8 = fcb[ch + 8];
#pragma unroll
        for (int ni = 0; ni < 4; ni++) {
            int tA = t0 + wn * 32 + ni * 8 + 2 * tg;
            bool v0 = (tA < len), v1 = (tA + 1 < len);
            size_t r0o = ((size_t)tA * BB + j) * DD;
            size_t r1o = ((size_t)(tA + 1) * BB + j) * DD;
            xout[r0o + ch]     = v0 ? c[mi][ni].x + b0 : 0.f;
            xout[r1o + ch]     = v1 ? c[mi][ni].y + b0 : 0.f;
            xout[r0o + ch + 8] = v0 ? c[mi][ni].z + b8 : 0.f;
            xout[r1o + ch + 8] = v1 ? c[mi][ni].w + b8 : 0.f;
        }
    }
}

// GEMM2: G[dir][j,t,ch] = x[t,j,:] @ w_ih[dir]^T — B from g_xfrag
__global__ void __launch_bounds__(128) k_gemm2() {
    __shared__ uint4 As[1024];
    __shared__ uint4 Bsm[1024];

    int dir = blockIdx.z;
    int j   = blockIdx.y >> 3;
    int t0i = blockIdx.y & 7;
    int t0  = t0i * 64;
    int m0  = blockIdx.x * 64;
    int tid = threadIdx.x;
    int len = g_lens[j];
    if (t0 >= len) return;

    int lane = tid & 31;
    int w    = tid >> 5;
    int wm   = w >> 1, wn = w & 1;
    int g    = lane >> 2, tg = lane & 3;

    float4 c[2][4];
#pragma unroll
    for (int mi = 0; mi < 2; mi++)
#pragma unroll
        for (int ni = 0; ni < 4; ni++) c[mi][ni] = make_float4(0.f,0.f,0.f,0.f);

    const uint4* wbase = g_wih[dir];
    const uint4* xbase = g_xfrag + ((size_t)((j * 8 + t0i) * 16)) * 1024;
    uint4 areg[8], breg[8];
    {
        const uint4* at = wbase + ((size_t)blockIdx.x * 16 + 0) * 1024;
#pragma unroll
        for (int u = 0; u < 8; u++) areg[u] = at[tid + 128 * u];
#pragma unroll
        for (int u = 0; u < 8; u++) breg[u] = xbase[tid + 128 * u];
    }

    for (int kt = 0; kt < 16; kt++) {
        __syncthreads();
#pragma unroll
        for (int u = 0; u < 8; u++) As[tid + 128 * u] = areg[u];
#pragma unroll
        for (int u = 0; u < 8; u++) Bsm[tid + 128 * u] = breg[u];
        __syncthreads();
        if (kt + 1 < 16) {
            const uint4* at = wbase + ((size_t)blockIdx.x * 16 + kt + 1) * 1024;
            const uint4* bt = xbase + (size_t)(kt + 1) * 1024;
#pragma unroll
            for (int u = 0; u < 8; u++) areg[u] = at[tid + 128 * u];
#pragma unroll
            for (int u = 0; u < 8; u++) breg[u] = bt[tid + 128 * u];
        }
        mma_ktile(As, Bsm, c, wm, wn, lane, g, tg);
    }

    float* Gd = g_G + (size_t)dir * GSZ;
#pragma unroll
    for (int mi = 0; mi < 2; mi++) {
        int ch = m0 + wm * 32 + mi * 16 + g;
#pragma unroll
        for (int ni = 0; ni < 4; ni++) {
            int tA = t0 + wn * 32 + ni * 8 + 2 * tg;
            size_t r0o = ((size_t)j * TT + tA) * G4H;
            size_t r1o = ((size_t)j * TT + tA + 1) * G4H;
            Gd[r0o + ch]     = c[mi][ni].x;
            Gd[r1o + ch]     = c[mi][ni].y;
            Gd[r0o + ch + 8] = c[mi][ni].z;
            Gd[r1o + ch + 8] = c[mi][ni].w;
        }
    }
}

// ---------------- scan dot-iteration body -------------------------------
__device__ __forceinline__ void dot_iter(const float* hbase,
                                         const ulonglong2* warr,
                                         float* psts, int b) {
    const ulonglong2* hp = (const ulonglong2*)(hbase + b * 544);
    unsigned long long a0 = 0, a1 = 0;
#pragma unroll
    for (int jj = 0; jj < 16; jj++) {
        ulonglong2 h2 = hp[jj];
        FMA2(a0, h2.x, warr[jj].x);
        FMA2(a1, h2.y, warr[jj].y);
    }
    psts[b * 36] = sum2(a0) + sum2(a1);
}

// ---------------- persistent scan kernel (v9: mid-dot poll + fast math) -
__global__ void __launch_bounds__(256, 1) k_scan(
    const float* __restrict__ c0, const float* __restrict__ h0,
    const float* __restrict__ whhf, const float* __restrict__ whhb,
    const float* __restrict__ bihf, const float* __restrict__ bhhf,
    const float* __restrict__ bihb, const float* __restrict__ bhhb,
    float* __restrict__ out) {
    __shared__ float h_s[2][8 * 544];
    __shared__ float g_sm[2][8 * 36];
    __shared__ float part[8 * 288];

    int bid  = blockIdx.x;
    int dir  = bid >> 6;
    int ctad = bid & 63;
    int hcb  = ctad * 8;
    int tid  = threadIdx.x;
    int w    = tid >> 5;
    int lane = tid & 31;
    int g4   = lane & 3;
    int ks   = lane >> 2;
    int hc   = hcb + w;

    const float* whh = dir ? whhb : whhf;
    ulonglong2 warr[16];
    {
        const float* wrow = whh + (size_t)(g4 * HH + hc) * HH + ks * 64;
#pragma unroll
        for (int i = 0; i < 16; i++) {
            float4 v = *(const float4*)(wrow + i * 4);
            warr[i].x = packf2(v.x, v.y);
            warr[i].y = packf2(v.z, v.w);
        }
    }
    float bias[4];
    {
        const float* bih = dir ? bihb : bihf;
        const float* bhh = dir ? bhhb : bhhf;
#pragma unroll
        for (int q = 0; q < 4; q++)
            bias[q] = bih[q * HH + hc] + bhh[q * HH + hc];
    }

    float creg[4], hreg[4];
    int   lenp[4];
    if (lane < 8) {
#pragma unroll
        for (int g = 0; g < 4; g++) {
            int b = g * 8 + lane;
            lenp[g] = g_lens[b];
            creg[g] = c0[dir * 16384 + b * HH + hc];
            hreg[g] = h0[dir * 16384 + b * HH + hc];
        }
    }

    int lb  = tid >> 5;
    int lg  = (tid & 31) >> 3;
    int lch = tid & 7;
    const float* Gd = g_G + (size_t)dir * GSZ;
    int lenG4[4];
#pragma unroll
    for (int g = 0; g < 4; g++) lenG4[g] = g_lens[g * 8 + lb];

    int glen[4];
#pragma unroll
    for (int g = 0; g < 4; g++) glen[g] = g_lens[g * 8];
    int maxlen = glen[0];

    {
        const float* hin = &g_hring[dir][0][0][0];
#pragma unroll
        for (int i = 0; i < 4; i++) {
            int idx = tid + 256 * i;
            float4 v = __ldcg((const float4*)&hin[idx * 4]);
            int b = idx >> 7;
            int k = (idx & 127) * 4;
            *(float4*)&h_s[0][b * 544 + (k >> 6) * 68 + (k & 63)] = v;
        }
        float gv = 0.f;
        if (0 < lenG4[0]) {
            int tt0 = dir ? (lenG4[0] - 1) : 0;
            gv = __ldg(&Gd[((size_t)lb * TT + tt0) * G4H + lg * HH + hcb + lch]);
        }
        g_sm[0][lb * 36 + lg * 8 + lch] = gv;
    }
    __syncthreads();

    int s = 0, g = 0, buf = 0;
    for (;;) {
        int ns = s, ng = g + 1;
        if (ng == 4 || ns >= glen[ng]) { ns = s + 1; ng = 0; }
        bool have_next = (ns < maxlen);
        bool can_pre   = have_next && !(ns == s + 1 && g == 0);

        const float* hbase = &h_s[buf][0] + ks * 68;
        float* psts = part + w * 288 + lane;

        // ---- dot first 2 iters (covers the poll's L2 latency) ----
        dot_iter(hbase, warr, psts, 0);
        dot_iter(hbase, warr, psts, 1);

        // ---- poll + prefetch next tick (latency hides under dot tail) ----
        float4 hpre[4];
        float  gpre = 0.f;
        if (can_pre) {
            if (ns > 0) {
                const unsigned* fp = &g_done[dir][ns - 1][ng];
                unsigned v;
                for (;;) {
                    asm volatile("ld.global.cg.u32 %0, [%1];"
                                 : "=r"(v) : "l"(fp));
                    if (v >= 64u) break;
                    __nanosleep(20);
                }
            }
            const float* hin = &g_hring[dir][ns & 3][ng * 8][0];
#pragma unroll
            for (int i = 0; i < 4; i++) {
                int idx = tid + 256 * i;
                hpre[i] = __ldcg((const float4*)&hin[idx * 4]);
            }
            if (ns < lenG4[ng]) {
                int bG = ng * 8 + lb;
                int tt = dir ? (lenG4[ng] - 1 - ns) : ns;
                gpre = __ldg(&Gd[((size_t)bG * TT + tt) * G4H +
                                 lg * HH + hcb + lch]);
            }
        }

        // ---- dot remaining 6 iters ----
#pragma unroll 2
        for (int b = 2; b < 8; b++) dot_iter(hbase, warr, psts, b);
        __syncwarp();

        // ---- pointwise (fast math) ----
        if (lane < 8) {
            int  b      = g * 8 + lane;
            bool active = (s < lenp[g]);
            const float4* pp = (const float4*)(part + w * 288 + lane * 36);
            float4 s4 = pp[0];
#pragma unroll
            for (int jq = 1; jq < 8; jq++) {
                float4 t = pp[jq];
                s4.x += t.x; s4.y += t.y; s4.z += t.z; s4.w += t.w;
            }
            float gi = s4.x + g_sm[buf][lane * 36 + 0 * 8 + w] + bias[0];
            float gf = s4.y + g_sm[buf][lane * 36 + 1 * 8 + w] + bias[1];
            float gg = s4.z + g_sm[buf][lane * 36 + 2 * 8 + w] + bias[2];
            float go = s4.w + g_sm[buf][lane * 36 + 3 * 8 + w] + bias[3];
            float i_ = fast_sigmoid(gi);
            float f_ = fast_sigmoid(gf);
            float g_ = fast_tanh(gg);
            float o_ = fast_sigmoid(go);
            float cn = f_ * creg[g] + i_ * g_;
            float hn = o_ * fast_tanh(cn);
            if (active) {
                creg[g] = cn; hreg[g] = hn;
                if (dir == 0) {
                    out[OUT_OFF + ((size_t)s * BB + b) * 1024 + hc] = hn;
                } else {
                    int tw = lenp[g] - 1 - s;
                    out[OUT_OFF + ((size_t)tw * BB + b) * 1024 + 512 + hc] = hn;
                }
            }
            g_hring[dir][(s + 1) & 3][b][hc] = hreg[g];
        }

        if (can_pre) {
#pragma unroll
            for (int i = 0; i < 4; i++) {
                int idx = tid + 256 * i;
                int b = idx >> 7;
                int k = (idx & 127) * 4;
                *(float4*)&h_s[buf ^ 1][b * 544 + (k >> 6) * 68 + (k & 63)]
                    = hpre[i];
            }
            g_sm[buf ^ 1][lb * 36 + lg * 8 + lch] = gpre;
        }

        __syncthreads();
        if (tid == 0) {
            __threadfence();
            atomicAdd(&g_done[dir][s][g], 1u);
        }

        if (!have_next) break;

        if (!can_pre) {
            const unsigned* fp = &g_done[dir][ns - 1][ng];
            unsigned v;
            for (;;) {
                asm volatile("ld.global.cg.u32 %0, [%1];" : "=r"(v) : "l"(fp));
                if (v >= 64u) break;
                __nanosleep(20);
            }
            const float* hin = &g_hring[dir][ns & 3][ng * 8][0];
#pragma unroll
            for (int i = 0; i < 4; i++) {
                int idx = tid + 256 * i;
                float4 hv = __ldcg((const float4*)&hin[idx * 4]);
                int b = idx >> 7;
                int k = (idx & 127) * 4;
                *(float4*)&h_s[buf ^ 1][b * 544 + (k >> 6) * 68 + (k & 63)]
                    = hv;
            }
            float gv = 0.f;
            if (ns < lenG4[ng]) {
                int bG = ng * 8 + lb;
                int tt = dir ? (lenG4[ng] - 1 - ns) : ns;
                gv = __ldg(&Gd[((size_t)bG * TT + tt) * G4H +
                               lg * HH + hcb + lch]);
            }
            g_sm[buf ^ 1][lb * 36 + lg * 8 + lch] = gv;
            __syncthreads();
        }

        s = ns; g = ng; buf ^= 1;
    }

    if (lane < 8) {
#pragma unroll
        for (int g = 0; g < 4; g++) {
            int b = g * 8 + lane;
            out[HN_OFF + dir * 16384 + b * HH + hc] = hreg[g];
            out[CN_OFF + dir * 16384 + b * HH + hc] = creg[g];
        }
    }
}

// ---------------- launcher ----------------------------------------------
extern "C" void kernel_launch(void* const* d_in, const int* in_sizes, int n_in,
                              void* d_out, int out_size) {
    const float* cnn  = (const float*)d_in[0];
    const float* fcw  = (const float*)d_in[1];
    const float* fcb  = (const float*)d_in[2];
    const float* h0   = (const float*)d_in[3];
    const float* c0   = (const float*)d_in[4];
    const float* wihf = (const float*)d_in[5];
    const float* whhf = (const float*)d_in[6];
    const float* bihf = (const float*)d_in[7];
    const float* bhhf = (const float*)d_in[8];
    const float* wihb = (const float*)d_in[9];
    const float* whhb = (const float*)d_in[10];
    const float* bihb = (const float*)d_in[11];
    const float* bihb2= (const float*)d_in[12];
    const int* seq_lens = (const int*)d_in[13];
    const int* lookup   = (const int*)d_in[14];
    const float* bhhb = bihb2;
    float* out = (float*)d_out;

    k_reset<<<1, 256>>>(seq_lens, h0, out);
    k_zero<<<16384, 256>>>(out);
    k_prep<<<dim3(2048, 3), 256>>>(fcw, wihf, wihb);
    k_prepx1<<<65536, 256>>>(cnn, lookup);
    k_gemm1<<<dim3(8, 8, 32), 128>>>(fcb, out + X_OFF);
    k_prepx<<<16384, 256>>>(out + X_OFF);
    k_gemm2<<<dim3(32, 256, 2), 128>>>();
    k_scan<<<128, 256>>>(c0, h0, whhf, whhb, bihf, bhhf, bihb, bhhb, out);
}

// round 17
// speedup vs baseline: 1.1201x; 1.0019x over previous
#include <cuda_runtime.h>
#include <cstdint>

// Problem dims
#define TT    512
#define BB    32
#define DD    512
#define HH    512
#define FEAT  2048
#define G4H   2048   // 4*H

// Output layout (fp32, tuple order: out, h_n, c_n, x, lens_s)
#define OUT_OFF  0
#define HN_OFF   16777216
#define CN_OFF   (16777216 + 32768)
#define X_OFF    (16777216 + 65536)
#define LENS_OFF (X_OFF + 8388608)

#define GSZ       (512*32*2048)        // per-direction G size (floats)
#define WCHUNKS   524288               // frag chunks per weight matrix
#define XCHUNKS   (4096 * 1024)        // x frag tiles: 32j * 8t0 * 16kt
#define X1CHUNKS  (16384 * 1024)       // cnn frag tiles: 32j * 8t0 * 64kt

// ---------------- device scratch ---------------------------------------
__device__ float    g_G[2 * GSZ];          // input-gate preactivations (268MB)
__device__ float    g_hring[2][4][BB][HH]; // h ring buffer, depth 4
__device__ unsigned g_done[2][TT][4];      // per (dir, step, group) counters
__device__ int      g_order[BB];
__device__ int      g_lens[BB];
__device__ uint4    g_wfc[WCHUNKS];        // fc_w   frag-layout (hi/lo tf32)
__device__ uint4    g_wih[2][WCHUNKS];     // w_ih_f / w_ih_b frag-layout
__device__ uint4    g_xfrag[XCHUNKS];      // x in B-frag layout (64MB)
__device__ uint4    g_x1frag[X1CHUNKS];    // gathered cnn in B-frag (256MB)

// ---------------- helpers ----------------------------------------------
__device__ __forceinline__ uint32_t f2tf32(float v) {
    uint32_t r;
    asm("cvt.rna.tf32.f32 %0, %1;" : "=r"(r) : "f"(v));
    return r;
}

__device__ __forceinline__ void mma_tf32(float4& c, const uint4& a,
                                         uint32_t b0, uint32_t b1) {
    asm volatile(
        "mma.sync.aligned.m16n8k8.row.col.f32.tf32.tf32.f32 "
        "{%0,%1,%2,%3}, {%4,%5,%6,%7}, {%8,%9}, {%0,%1,%2,%3};"
        : "+f"(c.x), "+f"(c.y), "+f"(c.z), "+f"(c.w)
        : "r"(a.x), "r"(a.y), "r"(a.z), "r"(a.w), "r"(b0), "r"(b1));
}

#define FMA2(acc, a, b) \
    asm("fma.rn.f32x2 %0, %1, %2, %0;" : "+l"(acc) : "l"(a), "l"(b))

__device__ __forceinline__ float sum2(unsigned long long v) {
    float lo, hi;
    asm("mov.b64 {%0,%1}, %2;" : "=f"(lo), "=f"(hi) : "l"(v));
    return lo + hi;
}

__device__ __forceinline__ unsigned long long packf2(float a, float b) {
    unsigned long long u;
    asm("mov.b64 %0, {%1,%2};" : "=l"(u) : "f"(a), "f"(b));
    return u;
}

__device__ __forceinline__ float fast_sigmoid(float x) {
    return __fdividef(1.f, 1.f + __expf(-x));
}
__device__ __forceinline__ float fast_tanh(float x) {
    float t = __expf(2.f * fabsf(x));
    float r = 1.f - __fdividef(2.f, t + 1.f);
    return copysignf(r, x);
}

// ---------------- reset / sort kernel ----------------------------------
__global__ void k_reset(const int* __restrict__ seq_lens,
                        const float* __restrict__ h0,
                        float* __restrict__ out) {
    int tid = threadIdx.x;
    if (tid == 0) {
        unsigned used = 0u;
        for (int pos = 0; pos < BB; pos++) {
            int best = -1, bl = -1;
            for (int i = 0; i < BB; i++) {
                if (used & (1u << i)) continue;
                int L = seq_lens[i];
                if (L > bl) { bl = L; best = i; }
            }
            used |= 1u << best;
            g_order[pos] = best;
            g_lens[pos]  = bl;
            out[LENS_OFF + pos] = (float)bl;
        }
    }
    for (int i = tid; i < 2 * TT * 4; i += blockDim.x)
        ((unsigned*)g_done)[i] = 0u;
    for (int i = tid; i < 2 * 16384; i += blockDim.x) {
        int dir = i >> 14;
        int r   = i & 16383;
        g_hring[dir][0][r >> 9][r & 511] = h0[i];
    }
}

// ---------------- bulk zero of the `out` region -------------------------
__global__ void __launch_bounds__(256) k_zero(float* __restrict__ out) {
    size_t i = ((size_t)blockIdx.x * 256 + threadIdx.x) * 4;
    *(float4*)&out[OUT_OFF + i] = make_float4(0.f, 0.f, 0.f, 0.f);
}

// ---------------- weight pre-conversion to frag layout ------------------
__global__ void __launch_bounds__(256) k_prep(
    const float* __restrict__ fcw, const float* __restrict__ wihf,
    const float* __restrict__ wihb) {
    int z = blockIdx.y;
    const float* src = (z == 0) ? fcw : ((z == 1) ? wihf : wihb);
    uint4* dst = (z == 0) ? g_wfc : g_wih[z - 1];
    int K     = (z == 0) ? FEAT : DD;
    int nKtm1 = (z == 0) ? 63 : 15;
    int nKtsh = (z == 0) ? 6 : 4;

    int c    = blockIdx.x * 256 + threadIdx.x;
    int lane = c & 31;
    int hl   = (c >> 5) & 1;
    int s    = (c >> 6) & 3;
    int q    = (c >> 8) & 3;
    int tile = c >> 10;
    int qt   = tile & nKtm1;
    int r64  = tile >> nKtsh;
    int g    = lane >> 2, tg = lane & 3;
    int m0   = r64 * 64 + s * 16;
    int kk   = qt * 32 + q * 8 + tg;

    float v0 = src[(size_t)(m0 + g)     * K + kk];
    float v1 = src[(size_t)(m0 + g + 8) * K + kk];
    float v2 = src[(size_t)(m0 + g)     * K + kk + 4];
    float v3 = src[(size_t)(m0 + g + 8) * K + kk + 4];
    uint4 o;
    if (hl == 0) {
        o.x = f2tf32(v0); o.y = f2tf32(v1); o.z = f2tf32(v2); o.w = f2tf32(v3);
    } else {
        o.x = f2tf32(v0 - __uint_as_float(f2tf32(v0)));
        o.y = f2tf32(v1 - __uint_as_float(f2tf32(v1)));
        o.z = f2tf32(v2 - __uint_as_float(f2tf32(v2)));
        o.w = f2tf32(v3 - __uint_as_float(f2tf32(v3)));
    }
    dst[c] = o;
}

// ---------------- x pre-conversion to B-frag layout (GEMM2 B) -----------
__global__ void __launch_bounds__(256) k_prepx(const float* __restrict__ x) {
    int c    = blockIdx.x * 256 + threadIdx.x;
    int tile = c >> 10;
    int rem  = c & 1023;
    int q  = rem >> 8;
    int r  = (rem >> 2) & 63;
    int sw = rem & 3;
    int xr = (r & 3) ^ ((r >> 2) & 3);
    int t2 = sw ^ xr;
    int kt  = tile & 15;
    int t0i = (tile >> 4) & 7;
    int j   = tile >> 7;
    int t   = t0i * 64 + r;
    int k0  = kt * 32 + q * 8;
    const float* row = &x[((size_t)t * BB + j) * DD];
    float v0 = row[k0 + t2];
    float v1 = row[k0 + t2 + 4];
    uint4 o;
    o.x = f2tf32(v0);
    o.y = f2tf32(v1);
    o.z = f2tf32(v0 - __uint_as_float(o.x));
    o.w = f2tf32(v1 - __uint_as_float(o.y));
    g_xfrag[c] = o;
}

// ---------------- gathered-cnn pre-conversion (GEMM1 B) -----------------
__global__ void __launch_bounds__(256) k_prepx1(
    const float* __restrict__ cnn, const int* __restrict__ lookup) {
    int c    = blockIdx.x * 256 + threadIdx.x;
    int tile = c >> 10;               // (j*8 + t0i)*64 + kt
    int rem  = c & 1023;
    int q  = rem >> 8;
    int r  = (rem >> 2) & 63;
    int sw = rem & 3;
    int xr = (r & 3) ^ ((r >> 2) & 3);
    int t2 = sw ^ xr;
    int kt  = tile & 63;
    int t0i = (tile >> 6) & 7;
    int j   = tile >> 9;
    int len = g_lens[j];
    if (t0i * 64 >= len) return;      // fully masked tile: gemm1 skips it
    int t   = t0i * 64 + r;
    int img = lookup[g_order[j] * TT + t];
    int k0  = kt * 32 + q * 8;
    const float* row = &cnn[(size_t)img * FEAT + k0];
    float v0 = row[t2];
    float v1 = row[t2 + 4];
    uint4 o;
    o.x = f2tf32(v0);
    o.y = f2tf32(v1);
    o.z = f2tf32(v0 - __uint_as_float(o.x));
    o.w = f2tf32(v1 - __uint_as_float(o.y));
    g_x1frag[c] = o;
}

// ================= MMA GEMMs: 128(M) x 64(N) tiles, 256 threads ========
// As: 2048 chunks (two 64-row frag tiles), Bsm: 1024 chunks.
__device__ __forceinline__ void mma_ktile128(const uint4* As,
                                             const uint4* Bsm,
                                             float4 c[2][4], int wm, int wn,
                                             int lane, int g, int tg) {
#pragma unroll
    for (int q = 0; q < 4; q++) {
        uint4 ah[2], al[2], bq[4];
#pragma unroll
        for (int mi = 0; mi < 2; mi++) {
            int s    = wm * 2 + mi;            // 0..7
            int half = s >> 2, sl = s & 3;
            ah[mi] = As[half * 1024 + ((q * 4 + sl) * 2 + 0) * 32 + lane];
            al[mi] = As[half * 1024 + ((q * 4 + sl) * 2 + 1) * 32 + lane];
        }
#pragma unroll
        for (int ni = 0; ni < 4; ni++) {
            int rr = wn * 32 + ni * 8 + g;
            int sw = tg ^ (rr & 3) ^ ((rr >> 2) & 3);
            bq[ni] = Bsm[q * 256 + rr * 4 + sw];
        }
#pragma unroll
        for (int mi = 0; mi < 2; mi++)
#pragma unroll
            for (int ni = 0; ni < 4; ni++) {
                mma_tf32(c[mi][ni], ah[mi], bq[ni].x, bq[ni].y);
                mma_tf32(c[mi][ni], ah[mi], bq[ni].z, bq[ni].w);
                mma_tf32(c[mi][ni], al[mi], bq[ni].x, bq[ni].y);
            }
    }
}

// GEMM1: x[t,j,ch] = mask * (cnn[lookup[order[j],t]] @ fc_w^T + fc_b)[ch]
// grid (4, 8, 32): m0 = bx*128 over DD, t0 = by*64, j = bz
__global__ void __launch_bounds__(256) k_gemm1(
    const float* __restrict__ fcb, float* __restrict__ xout) {
    __shared__ uint4 As[2048];
    __shared__ uint4 Bsm[1024];

    int j   = blockIdx.z;
    int t0i = blockIdx.y;
    int t0  = t0i * 64;
    int m0  = blockIdx.x * 128;
    int tid = threadIdx.x;
    int len = g_lens[j];

    if (t0 >= len) {
        for (int i = tid; i < 2048; i += 256) {
            int r  = i >> 5;
            int cc = (i & 31) * 4;
            int t  = t0 + r;
            *(float4*)&xout[((size_t)t * BB + j) * DD + m0 + cc] =
                make_float4(0.f, 0.f, 0.f, 0.f);
        }
        return;
    }

    int lane = tid & 31;
    int w    = tid >> 5;            // 0..7
    int wm   = w >> 1, wn = w & 1;  // wm 0..3, wn 0..1
    int g    = lane >> 2, tg = lane & 3;

    float4 c[2][4];
#pragma unroll
    for (int mi = 0; mi < 2; mi++)
#pragma unroll
        for (int ni = 0; ni < 4; ni++) c[mi][ni] = make_float4(0.f,0.f,0.f,0.f);

    // A: frag tiles r64 = 2*bx and 2*bx+1, nKt = 64
    const uint4* at0 = g_wfc + ((size_t)(2 * blockIdx.x)     * 64) * 1024;
    const uint4* at1 = g_wfc + ((size_t)(2 * blockIdx.x + 1) * 64) * 1024;
    const uint4* xbase = g_x1frag + ((size_t)((j * 8 + t0i) * 64)) * 1024;

    uint4 areg[8], breg[4];
    {
#pragma unroll
        for (int u = 0; u < 4; u++) areg[u]     = at0[tid + 256 * u];
#pragma unroll
        for (int u = 0; u < 4; u++) areg[4 + u] = at1[tid + 256 * u];
#pragma unroll
        for (int u = 0; u < 4; u++) breg[u] = xbase[tid + 256 * u];
    }

    for (int kt = 0; kt < 64; kt++) {
        __syncthreads();
#pragma unroll
        for (int u = 0; u < 4; u++) As[tid + 256 * u]        = areg[u];
#pragma unroll
        for (int u = 0; u < 4; u++) As[1024 + tid + 256 * u] = areg[4 + u];
#pragma unroll
        for (int u = 0; u < 4; u++) Bsm[tid + 256 * u] = breg[u];
        __syncthreads();
        if (kt + 1 < 64) {
            const uint4* a0 = at0 + (size_t)(kt + 1) * 1024;
            const uint4* a1 = at1 + (size_t)(kt + 1) * 1024;
            const uint4* bt = xbase + (size_t)(kt + 1) * 1024;
#pragma unroll
            for (int u = 0; u < 4; u++) areg[u]     = a0[tid + 256 * u];
#pragma unroll
            for (int u = 0; u < 4; u++) areg[4 + u] = a1[tid + 256 * u];
#pragma unroll
            for (int u = 0; u < 4; u++) breg[u] = bt[tid + 256 * u];
        }
        mma_ktile128(As, Bsm, c, wm, wn, lane, g, tg);
    }

#pragma unroll
    for (int mi = 0; mi < 2; mi++) {
        int ch  = m0 + wm * 32 + mi * 16 + g;
        float b0 = fcb[ch], b8 = fcb[ch + 8];
#pragma unroll
        for (int ni = 0; ni < 4; ni++) {
            int tA = t0 + wn * 32 + ni * 8 + 2 * tg;
            bool v0 = (tA < len), v1 = (tA + 1 < len);
            size_t r0o = ((size_t)tA * BB + j) * DD;
            size_t r1o = ((size_t)(tA + 1) * BB + j) * DD;
            xout[r0o + ch]     = v0 ? c[mi][ni].x + b0 : 0.f;
            xout[r1o + ch]     = v1 ? c[mi][ni].y + b0 : 0.f;
            xout[r0o + ch + 8] = v0 ? c[mi][ni].z + b8 : 0.f;
            xout[r1o + ch + 8] = v1 ? c[mi][ni].w + b8 : 0.f;
        }
    }
}

// GEMM2: G[dir][j,t,ch] = x[t,j,:] @ w_ih[dir]^T — B from g_xfrag
// grid (16, 256, 2): m0 = bx*128 over G4H
__global__ void __launch_bounds__(256) k_gemm2() {
    __shared__ uint4 As[2048];
    __shared__ uint4 Bsm[1024];

    int dir = blockIdx.z;
    int j   = blockIdx.y >> 3;
    int t0i = blockIdx.y & 7;
    int t0  = t0i * 64;
    int m0  = blockIdx.x * 128;
    int tid = threadIdx.x;
    int len = g_lens[j];
    if (t0 >= len) return;

    int lane = tid & 31;
    int w    = tid >> 5;
    int wm   = w >> 1, wn = w & 1;
    int g    = lane >> 2, tg = lane & 3;

    float4 c[2][4];
#pragma unroll
    for (int mi = 0; mi < 2; mi++)
#pragma unroll
        for (int ni = 0; ni < 4; ni++) c[mi][ni] = make_float4(0.f,0.f,0.f,0.f);

    const uint4* wbase = g_wih[dir];
    const uint4* at0 = wbase + ((size_t)(2 * blockIdx.x)     * 16) * 1024;
    const uint4* at1 = wbase + ((size_t)(2 * blockIdx.x + 1) * 16) * 1024;
    const uint4* xbase = g_xfrag + ((size_t)((j * 8 + t0i) * 16)) * 1024;

    uint4 areg[8], breg[4];
    {
#pragma unroll
        for (int u = 0; u < 4; u++) areg[u]     = at0[tid + 256 * u];
#pragma unroll
        for (int u = 0; u < 4; u++) areg[4 + u] = at1[tid + 256 * u];
#pragma unroll
        for (int u = 0; u < 4; u++) breg[u] = xbase[tid + 256 * u];
    }

    for (int kt = 0; kt < 16; kt++) {
        __syncthreads();
#pragma unroll
        for (int u = 0; u < 4; u++) As[tid + 256 * u]        = areg[u];
#pragma unroll
        for (int u = 0; u < 4; u++) As[1024 + tid + 256 * u] = areg[4 + u];
#pragma unroll
        for (int u = 0; u < 4; u++) Bsm[tid + 256 * u] = breg[u];
        __syncthreads();
        if (kt + 1 < 16) {
            const uint4* a0 = at0 + (size_t)(kt + 1) * 1024;
            const uint4* a1 = at1 + (size_t)(kt + 1) * 1024;
            const uint4* bt = xbase + (size_t)(kt + 1) * 1024;
#pragma unroll
            for (int u = 0; u < 4; u++) areg[u]     = a0[tid + 256 * u];
#pragma unroll
            for (int u = 0; u < 4; u++) areg[4 + u] = a1[tid + 256 * u];
#pragma unroll
            for (int u = 0; u < 4; u++) breg[u] = bt[tid + 256 * u];
        }
        mma_ktile128(As, Bsm, c, wm, wn, lane, g, tg);
    }

    float* Gd = g_G + (size_t)dir * GSZ;
#pragma unroll
    for (int mi = 0; mi < 2; mi++) {
        int ch = m0 + wm * 32 + mi * 16 + g;
#pragma unroll
        for (int ni = 0; ni < 4; ni++) {
            int tA = t0 + wn * 32 + ni * 8 + 2 * tg;
            size_t r0o = ((size_t)j * TT + tA) * G4H;
            size_t r1o = ((size_t)j * TT + tA + 1) * G4H;
            Gd[r0o + ch]     = c[mi][ni].x;
            Gd[r1o + ch]     = c[mi][ni].y;
            Gd[r0o + ch + 8] = c[mi][ni].z;
            Gd[r1o + ch + 8] = c[mi][ni].w;
        }
    }
}

// ---------------- scan dot-iteration body -------------------------------
__device__ __forceinline__ void dot_iter(const float* hbase,
                                         const ulonglong2* warr,
                                         float* psts, int b) {
    const ulonglong2* hp = (const ulonglong2*)(hbase + b * 544);
    unsigned long long a0 = 0, a1 = 0;
#pragma unroll
    for (int jj = 0; jj < 16; jj++) {
        ulonglong2 h2 = hp[jj];
        FMA2(a0, h2.x, warr[jj].x);
        FMA2(a1, h2.y, warr[jj].y);
    }
    psts[b * 36] = sum2(a0) + sum2(a1);
}

// ---------------- persistent scan kernel (v9, R16-proven) ---------------
__global__ void __launch_bounds__(256, 1) k_scan(
    const float* __restrict__ c0, const float* __restrict__ h0,
    const float* __restrict__ whhf, const float* __restrict__ whhb,
    const float* __restrict__ bihf, const float* __restrict__ bhhf,
    const float* __restrict__ bihb, const float* __restrict__ bhhb,
    float* __restrict__ out) {
    __shared__ float h_s[2][8 * 544];
    __shared__ float g_sm[2][8 * 36];
    __shared__ float part[8 * 288];

    int bid  = blockIdx.x;
    int dir  = bid >> 6;
    int ctad = bid & 63;
    int hcb  = ctad * 8;
    int tid  = threadIdx.x;
    int w    = tid >> 5;
    int lane = tid & 31;
    int g4   = lane & 3;
    int ks   = lane >> 2;
    int hc   = hcb + w;

    const float* whh = dir ? whhb : whhf;
    ulonglong2 warr[16];
    {
        const float* wrow = whh + (size_t)(g4 * HH + hc) * HH + ks * 64;
#pragma unroll
        for (int i = 0; i < 16; i++) {
            float4 v = *(const float4*)(wrow + i * 4);
            warr[i].x = packf2(v.x, v.y);
            warr[i].y = packf2(v.z, v.w);
        }
    }
    float bias[4];
    {
        const float* bih = dir ? bihb : bihf;
        const float* bhh = dir ? bhhb : bhhf;
#pragma unroll
        for (int q = 0; q < 4; q++)
            bias[q] = bih[q * HH + hc] + bhh[q * HH + hc];
    }

    float creg[4], hreg[4];
    int   lenp[4];
    if (lane < 8) {
#pragma unroll
        for (int g = 0; g < 4; g++) {
            int b = g * 8 + lane;
            lenp[g] = g_lens[b];
            creg[g] = c0[dir * 16384 + b * HH + hc];
            hreg[g] = h0[dir * 16384 + b * HH + hc];
        }
    }

    int lb  = tid >> 5;
    int lg  = (tid & 31) >> 3;
    int lch = tid & 7;
    const float* Gd = g_G + (size_t)dir * GSZ;
    int lenG4[4];
#pragma unroll
    for (int g = 0; g < 4; g++) lenG4[g] = g_lens[g * 8 + lb];

    int glen[4];
#pragma unroll
    for (int g = 0; g < 4; g++) glen[g] = g_lens[g * 8];
    int maxlen = glen[0];

    {
        const float* hin = &g_hring[dir][0][0][0];
#pragma unroll
        for (int i = 0; i < 4; i++) {
            int idx = tid + 256 * i;
            float4 v = __ldcg((const float4*)&hin[idx * 4]);
            int b = idx >> 7;
            int k = (idx & 127) * 4;
            *(float4*)&h_s[0][b * 544 + (k >> 6) * 68 + (k & 63)] = v;
        }
        float gv = 0.f;
        if (0 < lenG4[0]) {
            int tt0 = dir ? (lenG4[0] - 1) : 0;
            gv = __ldg(&Gd[((size_t)lb * TT + tt0) * G4H + lg * HH + hcb + lch]);
        }
        g_sm[0][lb * 36 + lg * 8 + lch] = gv;
    }
    __syncthreads();

    int s = 0, g = 0, buf = 0;
    for (;;) {
        int ns = s, ng = g + 1;
        if (ng == 4 || ns >= glen[ng]) { ns = s + 1; ng = 0; }
        bool have_next = (ns < maxlen);
        bool can_pre   = have_next && !(ns == s + 1 && g == 0);

        const float* hbase = &h_s[buf][0] + ks * 68;
        float* psts = part + w * 288 + lane;

        // ---- dot first 2 iters (covers the poll's L2 latency) ----
        dot_iter(hbase, warr, psts, 0);
        dot_iter(hbase, warr, psts, 1);

        // ---- poll + prefetch next tick (latency hides under dot tail) ----
        float4 hpre[4];
        float  gpre = 0.f;
        if (can_pre) {
            if (ns > 0) {
                const unsigned* fp = &g_done[dir][ns - 1][ng];
                unsigned v;
                for (;;) {
                    asm volatile("ld.global.cg.u32 %0, [%1];"
                                 : "=r"(v) : "l"(fp));
                    if (v >= 64u) break;
                    __nanosleep(20);
                }
            }
            const float* hin = &g_hring[dir][ns & 3][ng * 8][0];
#pragma unroll
            for (int i = 0; i < 4; i++) {
                int idx = tid + 256 * i;
                hpre[i] = __ldcg((const float4*)&hin[idx * 4]);
            }
            if (ns < lenG4[ng]) {
                int bG = ng * 8 + lb;
                int tt = dir ? (lenG4[ng] - 1 - ns) : ns;
                gpre = __ldg(&Gd[((size_t)bG * TT + tt) * G4H +
                                 lg * HH + hcb + lch]);
            }
        }

        // ---- dot remaining 6 iters ----
#pragma unroll 2
        for (int b = 2; b < 8; b++) dot_iter(hbase, warr, psts, b);
        __syncwarp();

        // ---- pointwise (fast math) ----
        if (lane < 8) {
            int  b      = g * 8 + lane;
            bool active = (s < lenp[g]);
            const float4* pp = (const float4*)(part + w * 288 + lane * 36);
            float4 s4 = pp[0];
#pragma unroll
            for (int jq = 1; jq < 8; jq++) {
                float4 t = pp[jq];
                s4.x += t.x; s4.y += t.y; s4.z += t.z; s4.w += t.w;
            }
            float gi = s4.x + g_sm[buf][lane * 36 + 0 * 8 + w] + bias[0];
            float gf = s4.y + g_sm[buf][lane * 36 + 1 * 8 + w] + bias[1];
            float gg = s4.z + g_sm[buf][lane * 36 + 2 * 8 + w] + bias[2];
            float go = s4.w + g_sm[buf][lane * 36 + 3 * 8 + w] + bias[3];
            float i_ = fast_sigmoid(gi);
            float f_ = fast_sigmoid(gf);
            float g_ = fast_tanh(gg);
            float o_ = fast_sigmoid(go);
            float cn = f_ * creg[g] + i_ * g_;
            float hn = o_ * fast_tanh(cn);
            if (active) {
                creg[g] = cn; hreg[g] = hn;
                if (dir == 0) {
                    out[OUT_OFF + ((size_t)s * BB + b) * 1024 + hc] = hn;
                } else {
                    int tw = lenp[g] - 1 - s;
                    out[OUT_OFF + ((size_t)tw * BB + b) * 1024 + 512 + hc] = hn;
                }
            }
            g_hring[dir][(s + 1) & 3][b][hc] = hreg[g];
        }

        if (can_pre) {
#pragma unroll
            for (int i = 0; i < 4; i++) {
                int idx = tid + 256 * i;
                int b = idx >> 7;
                int k = (idx & 127) * 4;
                *(float4*)&h_s[buf ^ 1][b * 544 + (k >> 6) * 68 + (k & 63)]
                    = hpre[i];
            }
            g_sm[buf ^ 1][lb * 36 + lg * 8 + lch] = gpre;
        }

        __syncthreads();
        if (tid == 0) {
            __threadfence();
            atomicAdd(&g_done[dir][s][g], 1u);
        }

        if (!have_next) break;

        if (!can_pre) {
            // G first (never ring-dependent) so its latency overlaps the poll
            float gv = 0.f;
            if (ns < lenG4[ng]) {
                int bG = ng * 8 + lb;
                int tt = dir ? (lenG4[ng] - 1 - ns) : ns;
                gv = __ldg(&Gd[((size_t)bG * TT + tt) * G4H +
                               lg * HH + hcb + lch]);
            }
            const unsigned* fp = &g_done[dir][ns - 1][ng];
            unsigned v;
            for (;;) {
                asm volatile("ld.global.cg.u32 %0, [%1];" : "=r"(v) : "l"(fp));
                if (v >= 64u) break;
                __nanosleep(20);
            }
            const float* hin = &g_hring[dir][ns & 3][ng * 8][0];
#pragma unroll
            for (int i = 0; i < 4; i++) {
                int idx = tid + 256 * i;
                float4 hv = __ldcg((const float4*)&hin[idx * 4]);
                int b = idx >> 7;
                int k = (idx & 127) * 4;
                *(float4*)&h_s[buf ^ 1][b * 544 + (k >> 6) * 68 + (k & 63)]
                    = hv;
            }
            g_sm[buf ^ 1][lb * 36 + lg * 8 + lch] = gv;
            __syncthreads();
        }

        s = ns; g = ng; buf ^= 1;
    }

    if (lane < 8) {
#pragma unroll
        for (int g = 0; g < 4; g++) {
            int b = g * 8 + lane;
            out[HN_OFF + dir * 16384 + b * HH + hc] = hreg[g];
            out[CN_OFF + dir * 16384 + b * HH + hc] = creg[g];
        }
    }
}

// ---------------- launcher ----------------------------------------------
extern "C" void kernel_launch(void* const* d_in, const int* in_sizes, int n_in,
                              void* d_out, int out_size) {
    const float* cnn  = (const float*)d_in[0];
    const float* fcw  = (const float*)d_in[1];
    const float* fcb  = (const float*)d_in[2];
    const float* h0   = (const float*)d_in[3];
    const float* c0   = (const float*)d_in[4];
    const float* wihf = (const float*)d_in[5];
    const float* whhf = (const float*)d_in[6];
    const float* bihf = (const float*)d_in[7];
    const float* bhhf = (const float*)d_in[8];
    const float* wihb = (const float*)d_in[9];
    const float* whhb = (const float*)d_in[10];
    const float* bihb = (const float*)d_in[11];
    const float* bhhb = (const float*)d_in[12];
    const int* seq_lens = (const int*)d_in[13];
    const int* lookup   = (const int*)d_in[14];
    float* out = (float*)d_out;

    k_reset<<<1, 256>>>(seq_lens, h0, out);
    k_zero<<<16384, 256>>>(out);
    k_prep<<<dim3(2048, 3), 256>>>(fcw, wihf, wihb);
    k_prepx1<<<65536, 256>>>(cnn, lookup);
    k_gemm1<<<dim3(4, 8, 32), 256>>>(fcb, out + X_OFF);
    k_prepx<<<16384, 256>>>(out + X_OFF);
    k_gemm2<<<dim3(16, 256, 2), 256>>>();
    k_scan<<<128, 256>>>(c0, h0, whhf, whhb, bihf, bhhf, bihb, bhhb, out);
}